// round 1
// baseline (speedup 1.0000x reference)
#include <cuda_runtime.h>
#include <math.h>

#define S_LEN  2048
#define DMODEL 1024
#define NHEADS 16
#define DK     64
#define MAXB   2

// ---- scratch (device globals: allocation-free) ----
__device__ float g_q   [MAXB * NHEADS * S_LEN * DK];   // (B,H,S,Dk), pre-scaled by 1/8
__device__ float g_k   [MAXB * NHEADS * S_LEN * DK];
__device__ float g_v   [MAXB * NHEADS * S_LEN * DK];
__device__ float g_attn[MAXB * S_LEN * DMODEL];        // combined (B,S,H*Dk)

// ============================================================================
// SGEMM: C = (A[M,K] @ W[K,N] + bias[N]) * scale
// split==1: write to (B,H,S,Dk) layout (S_LEN=2048 rows per batch, Dk=64 per head)
// 64x64 block tile, BK=16, 256 threads, 4x4 per thread.
// ============================================================================
__global__ __launch_bounds__(256) void gemm_bias_kernel(
    const float* __restrict__ A, const float* __restrict__ W,
    const float* __restrict__ bias, float* __restrict__ C,
    int M, int N, int K, int split, float scale)
{
    __shared__ float a_s[64][20];   // [m][k], pad 20 keeps 16B alignment, no store conflicts
    __shared__ float b_s[16][64];   // [k][n]

    const int tid = threadIdx.x;
    const int tx = tid & 15, ty = tid >> 4;
    const int rowBase = blockIdx.y * 64;
    const int colBase = blockIdx.x * 64;

    const int la_r = tid >> 2;            // 0..63
    const int la_k = (tid & 3) << 2;      // 0,4,8,12
    const int lb_k = tid >> 4;            // 0..15
    const int lb_n = (tid & 15) << 2;     // 0..60

    float acc[4][4] = {};

    for (int kt = 0; kt < K; kt += 16) {
        float4 av = *(const float4*)&A[(rowBase + la_r) * K + kt + la_k];
        *(float4*)&a_s[la_r][la_k] = av;
        float4 bv = *(const float4*)&W[(kt + lb_k) * N + colBase + lb_n];
        *(float4*)&b_s[lb_k][lb_n] = bv;
        __syncthreads();

        #pragma unroll
        for (int k = 0; k < 16; k++) {
            float a0 = a_s[4*ty + 0][k];
            float a1 = a_s[4*ty + 1][k];
            float a2 = a_s[4*ty + 2][k];
            float a3 = a_s[4*ty + 3][k];
            float4 b4 = *(const float4*)&b_s[k][4*tx];
            acc[0][0] += a0*b4.x; acc[0][1] += a0*b4.y; acc[0][2] += a0*b4.z; acc[0][3] += a0*b4.w;
            acc[1][0] += a1*b4.x; acc[1][1] += a1*b4.y; acc[1][2] += a1*b4.z; acc[1][3] += a1*b4.w;
            acc[2][0] += a2*b4.x; acc[2][1] += a2*b4.y; acc[2][2] += a2*b4.z; acc[2][3] += a2*b4.w;
            acc[3][0] += a3*b4.x; acc[3][1] += a3*b4.y; acc[3][2] += a3*b4.z; acc[3][3] += a3*b4.w;
        }
        __syncthreads();
    }

    #pragma unroll
    for (int i = 0; i < 4; i++) {
        const int row = rowBase + 4*ty + i;
        #pragma unroll
        for (int j = 0; j < 4; j++) {
            const int col = colBase + 4*tx + j;
            float c = (acc[i][j] + bias[col]) * scale;
            if (split) {
                int b = row >> 11, s = row & 2047;
                int h = col >> 6,  d = col & 63;
                C[(((b << 4) + h) * S_LEN + s) * DK + d] = c;
            } else {
                C[row * N + col] = c;
            }
        }
    }
}

// ============================================================================
// Flash attention: one CTA per (64 q-rows, head, batch). Dk = 64.
// Shared tiles are XOR-swizzled so all inner-loop reads are conflict-free LDS.128.
// Layout: element (major, minor) at major*64 + (((minor>>2) ^ (major&15))<<2 | (minor&3))
// ============================================================================
__device__ __forceinline__ int swz(int major, int minor) {
    return major * 64 + ((((minor >> 2) ^ (major & 15)) << 2) | (minor & 3));
}
// base address of 4 consecutive minors (minor4 = minor/4)
__device__ __forceinline__ int swz4(int major, int minor4) {
    return major * 64 + ((minor4 ^ (major & 15)) << 2);
}

__global__ __launch_bounds__(256) void attn_kernel()
{
    __shared__ float qs [4096];   // (d major, q-row minor), q pre-scaled by 1/8
    __shared__ float kvs[4096];   // K phase: (d major, kv minor); V phase: (kv major, d minor)
    __shared__ float ps [4096];   // (kv major, q-row minor)

    const int tid = threadIdx.x;
    const int tx = tid & 15, ty = tid >> 4;
    const int q0 = blockIdx.x * 64;
    const int h  = blockIdx.y;
    const int b  = blockIdx.z;

    const float* qg = g_q + ((size_t)(b * NHEADS + h) * S_LEN) * DK;
    const float* kg = g_k + ((size_t)(b * NHEADS + h) * S_LEN) * DK;
    const float* vg = g_v + ((size_t)(b * NHEADS + h) * S_LEN) * DK;

    // load Q tile, transposed into (d, r)
    #pragma unroll
    for (int rr = 0; rr < 4; rr++) {
        int r = ty + 16 * rr;
        float4 v = *(const float4*)&qg[(q0 + r) * DK + 4 * tx];
        qs[swz(4*tx + 0, r)] = v.x;
        qs[swz(4*tx + 1, r)] = v.y;
        qs[swz(4*tx + 2, r)] = v.z;
        qs[swz(4*tx + 3, r)] = v.w;
    }

    float o[4][4] = {};
    float m[4] = {-1e30f, -1e30f, -1e30f, -1e30f};
    float l[4] = {};

    for (int kt = 0; kt < S_LEN / 64; kt++) {
        // load K tile transposed (d, kv)
        #pragma unroll
        for (int rr = 0; rr < 4; rr++) {
            int r = ty + 16 * rr;
            float4 v = *(const float4*)&kg[(kt * 64 + r) * DK + 4 * tx];
            kvs[swz(4*tx + 0, r)] = v.x;
            kvs[swz(4*tx + 1, r)] = v.y;
            kvs[swz(4*tx + 2, r)] = v.z;
            kvs[swz(4*tx + 3, r)] = v.w;
        }
        __syncthreads();

        // scores: s[i][j] = sum_d q[4ty+i][d] * k[4tx+j][d]   (q already /8)
        float s[4][4] = {};
        #pragma unroll
        for (int d = 0; d < 64; d++) {
            float4 qf = *(const float4*)&qs [swz4(d, ty)];
            float4 kf = *(const float4*)&kvs[swz4(d, tx)];
            s[0][0] += qf.x*kf.x; s[0][1] += qf.x*kf.y; s[0][2] += qf.x*kf.z; s[0][3] += qf.x*kf.w;
            s[1][0] += qf.y*kf.x; s[1][1] += qf.y*kf.y; s[1][2] += qf.y*kf.z; s[1][3] += qf.y*kf.w;
            s[2][0] += qf.z*kf.x; s[2][1] += qf.z*kf.y; s[2][2] += qf.z*kf.z; s[2][3] += qf.z*kf.w;
            s[3][0] += qf.w*kf.x; s[3][1] += qf.w*kf.y; s[3][2] += qf.w*kf.z; s[3][3] += qf.w*kf.w;
        }

        // online softmax (row groups of 16 lanes: xor offsets < 16 stay in group)
        #pragma unroll
        for (int i = 0; i < 4; i++) {
            float tm = fmaxf(fmaxf(s[i][0], s[i][1]), fmaxf(s[i][2], s[i][3]));
            #pragma unroll
            for (int off = 8; off; off >>= 1)
                tm = fmaxf(tm, __shfl_xor_sync(0xffffffffu, tm, off));
            float mn = fmaxf(m[i], tm);
            float corr = __expf(m[i] - mn);
            float ls = 0.f;
            #pragma unroll
            for (int j = 0; j < 4; j++) { s[i][j] = __expf(s[i][j] - mn); ls += s[i][j]; }
            #pragma unroll
            for (int off = 8; off; off >>= 1)
                ls += __shfl_xor_sync(0xffffffffu, ls, off);
            l[i] = l[i] * corr + ls;
            m[i] = mn;
            #pragma unroll
            for (int j = 0; j < 4; j++) o[i][j] *= corr;
            // write P to shared: (kv major = 4tx+j, q-row minor = 4ty+i)
            #pragma unroll
            for (int j = 0; j < 4; j++) ps[swz(4*tx + j, 4*ty + i)] = s[i][j];
        }
        __syncthreads();   // scores done reading kvs; ps fully written

        // load V tile row-major (kv major, d minor) into kvs
        #pragma unroll
        for (int rr = 0; rr < 4; rr++) {
            int r = ty + 16 * rr;
            float4 v = *(const float4*)&vg[(kt * 64 + r) * DK + 4 * tx];
            *(float4*)&kvs[swz4(r, tx)] = v;
        }
        __syncthreads();

        // o[i][j] += sum_kv P[4ty+i][kv] * V[kv][4tx+j]
        #pragma unroll
        for (int c = 0; c < 64; c++) {
            float4 pf = *(const float4*)&ps [swz4(c, ty)];
            float4 vf = *(const float4*)&kvs[swz4(c, tx)];
            o[0][0] += pf.x*vf.x; o[0][1] += pf.x*vf.y; o[0][2] += pf.x*vf.z; o[0][3] += pf.x*vf.w;
            o[1][0] += pf.y*vf.x; o[1][1] += pf.y*vf.y; o[1][2] += pf.y*vf.z; o[1][3] += pf.y*vf.w;
            o[2][0] += pf.z*vf.x; o[2][1] += pf.z*vf.y; o[2][2] += pf.z*vf.z; o[2][3] += pf.z*vf.w;
            o[3][0] += pf.w*vf.x; o[3][1] += pf.w*vf.y; o[3][2] += pf.w*vf.z; o[3][3] += pf.w*vf.w;
        }
        __syncthreads();   // before next tile overwrites kvs/ps
    }

    // epilogue: divide by l, write combined (B,S,H*Dk) layout
    float* og = g_attn + (size_t)b * S_LEN * DMODEL + h * DK;
    #pragma unroll
    for (int i = 0; i < 4; i++) {
        float inv = 1.0f / l[i];
        float4 w;
        w.x = o[i][0] * inv; w.y = o[i][1] * inv; w.z = o[i][2] * inv; w.w = o[i][3] * inv;
        *(float4*)&og[(size_t)(q0 + 4*ty + i) * DMODEL + 4 * tx] = w;
    }
}

// ============================================================================
extern "C" void kernel_launch(void* const* d_in, const int* in_sizes, int n_in,
                              void* d_out, int out_size)
{
    const float* Q  = (const float*)d_in[0];
    const float* K_ = (const float*)d_in[1];
    const float* V  = (const float*)d_in[2];
    const float* Wq = (const float*)d_in[3];
    const float* bq = (const float*)d_in[4];
    const float* Wk = (const float*)d_in[5];
    const float* bk = (const float*)d_in[6];
    const float* Wv = (const float*)d_in[7];
    const float* bv = (const float*)d_in[8];
    const float* Wo = (const float*)d_in[9];
    const float* bo = (const float*)d_in[10];

    int B = in_sizes[0] / (S_LEN * DMODEL);
    if (B > MAXB) B = MAXB;
    const int M = B * S_LEN;

    float *pq, *pk, *pv, *pa;
    cudaGetSymbolAddress((void**)&pq, g_q);
    cudaGetSymbolAddress((void**)&pk, g_k);
    cudaGetSymbolAddress((void**)&pv, g_v);
    cudaGetSymbolAddress((void**)&pa, g_attn);

    dim3 gg(DMODEL / 64, M / 64);
    gemm_bias_kernel<<<gg, 256>>>(Q,  Wq, bq, pq, M, DMODEL, DMODEL, 1, 0.125f);
    gemm_bias_kernel<<<gg, 256>>>(K_, Wk, bk, pk, M, DMODEL, DMODEL, 1, 1.0f);
    gemm_bias_kernel<<<gg, 256>>>(V,  Wv, bv, pv, M, DMODEL, DMODEL, 1, 1.0f);

    attn_kernel<<<dim3(S_LEN / 64, NHEADS, B), 256>>>();

    gemm_bias_kernel<<<gg, 256>>>(pa, Wo, bo, (float*)d_out, M, DMODEL, DMODEL, 0, 1.0f);
}

// round 3
// speedup vs baseline: 1.3629x; 1.3629x over previous
#include <cuda_runtime.h>
#include <cuda_bf16.h>
#include <math.h>
#include <stdint.h>

#define S_LEN  2048
#define DMODEL 1024
#define NHEADS 16
#define DK     64
#define MAXB   2
#define MMAX   (MAXB * S_LEN)      // 4096

// ---- scratch (device globals: allocation-free) ----
__device__ float g_q   [MAXB * NHEADS * S_LEN * DK];
__device__ float g_k   [MAXB * NHEADS * S_LEN * DK];
__device__ float g_v   [MAXB * NHEADS * S_LEN * DK];
__device__ float g_attn[MAXB * S_LEN * DMODEL];
// bf16 hi/lo planes: A row-major [M][K], W transposed [N][K]
__device__ __align__(16) __nv_bfloat16 g_a16[2ull * MMAX * DMODEL];            // 16 MB
__device__ __align__(16) __nv_bfloat16 g_w16[4][2ull * DMODEL * DMODEL];       // 4 x 4 MB

// ============================================================================
// helpers
// ============================================================================
__device__ __forceinline__ uint32_t smem_u32(const void* p) {
    uint32_t r;
    asm("{ .reg .u64 t; cvta.to.shared.u64 t, %1; cvt.u32.u64 %0, t; }" : "=r"(r) : "l"(p));
    return r;
}
__device__ __forceinline__ void split2(float v, __nv_bfloat16& h, __nv_bfloat16& l) {
    h = __float2bfloat16(v);
    l = __float2bfloat16(v - __bfloat162float(h));
}
__device__ __forceinline__ uint32_t pack2(__nv_bfloat16 a, __nv_bfloat16 b) {
    __nv_bfloat162 t = __halves2bfloat162(a, b);
    return *reinterpret_cast<uint32_t*>(&t);
}
__device__ __forceinline__ void cp16(uint32_t s, const void* g) {
    asm volatile("cp.async.cg.shared.global [%0], [%1], 16;" :: "r"(s), "l"(g));
}
__device__ __forceinline__ void cp_commit() {
    asm volatile("cp.async.commit_group;");
}
template <int N> __device__ __forceinline__ void cp_wait() {
    asm volatile("cp.async.wait_group %0;" :: "n"(N));
}
__device__ __forceinline__ void ldm_x4(uint32_t* r, uint32_t a) {
    asm volatile("ldmatrix.sync.aligned.m8n8.x4.shared.b16 {%0,%1,%2,%3}, [%4];"
                 : "=r"(r[0]), "=r"(r[1]), "=r"(r[2]), "=r"(r[3]) : "r"(a));
}
__device__ __forceinline__ void mma16816(float* d, const uint32_t* a, uint32_t b0, uint32_t b1) {
    asm volatile(
        "mma.sync.aligned.m16n8k16.row.col.f32.bf16.bf16.f32 "
        "{%0,%1,%2,%3}, {%4,%5,%6,%7}, {%8,%9}, {%0,%1,%2,%3};"
        : "+f"(d[0]), "+f"(d[1]), "+f"(d[2]), "+f"(d[3])
        : "r"(a[0]), "r"(a[1]), "r"(a[2]), "r"(a[3]), "r"(b0), "r"(b1));
}

// ============================================================================
// conversion: A[M,1024] fp32 -> hi/lo bf16 planes, row-major
// ============================================================================
__global__ __launch_bounds__(256) void conv_split_a(
    const float* __restrict__ A, __nv_bfloat16* __restrict__ dst, int M)
{
    int idx = blockIdx.x * 256 + threadIdx.x;      // one thread per 4 consecutive k
    if (idx >= M * 256) return;
    int row = idx >> 8, kg = idx & 255;
    float4 v = *(const float4*)(A + (size_t)row * DMODEL + kg * 4);
    __nv_bfloat16 h0, h1, h2, h3, l0, l1, l2, l3;
    split2(v.x, h0, l0); split2(v.y, h1, l1); split2(v.z, h2, l2); split2(v.w, h3, l3);
    size_t off = (size_t)row * DMODEL + kg * 4;
    size_t loPl = (size_t)M * DMODEL;
    *(uint2*)(dst + off)        = make_uint2(pack2(h0, h1), pack2(h2, h3));
    *(uint2*)(dst + loPl + off) = make_uint2(pack2(l0, l1), pack2(l2, l3));
}

// W[1024,1024] fp32 (k-major rows) -> transposed hi/lo planes [N][K]
__global__ __launch_bounds__(256) void conv_split_w(
    const float* __restrict__ W, __nv_bfloat16* __restrict__ dst)
{
    int idx = blockIdx.x * 256 + threadIdx.x;      // (kg, n); n fastest -> coalesced reads
    int kg = idx >> 10, n = idx & 1023;
    int k0 = kg * 4;
    float a0 = W[(size_t)(k0 + 0) * DMODEL + n];
    float a1 = W[(size_t)(k0 + 1) * DMODEL + n];
    float a2 = W[(size_t)(k0 + 2) * DMODEL + n];
    float a3 = W[(size_t)(k0 + 3) * DMODEL + n];
    __nv_bfloat16 h0, h1, h2, h3, l0, l1, l2, l3;
    split2(a0, h0, l0); split2(a1, h1, l1); split2(a2, h2, l2); split2(a3, h3, l3);
    size_t off = (size_t)n * DMODEL + k0;
    size_t loPl = (size_t)DMODEL * DMODEL;
    *(uint2*)(dst + off)        = make_uint2(pack2(h0, h1), pack2(h2, h3));
    *(uint2*)(dst + loPl + off) = make_uint2(pack2(l0, l1), pack2(l2, l3));
}

// ============================================================================
// mma.sync bf16x3 GEMM: C[M,1024] = (A*W + bias) * scale
// CTA 128x128, BK=32, 8 warps (2M x 4N), warp tile 64x32, cp.async double buffer.
// smem rows padded to 80B -> conflict-free ldmatrix (offsets mod 128 all distinct).
// ============================================================================
#define SROW   80            // bytes per 32-bf16 row (64 data + 16 pad)
#define PLANE  (128 * SROW)  // 10240 B
#define STAGE  (4 * PLANE)   // Ah Al Bh Bl = 40960 B
#define GEMM_SMEM (2 * STAGE)

__global__ __launch_bounds__(256) void gemm_mma(
    const __nv_bfloat16* __restrict__ aP, const __nv_bfloat16* __restrict__ wP,
    const float* __restrict__ bias, float* __restrict__ C,
    int M, int split, float scale)
{
    extern __shared__ unsigned char dyn[];
    const uint32_t sbase = smem_u32(dyn);

    const int tid = threadIdx.x, lane = tid & 31, wid = tid >> 5;
    const int mw = wid >> 2, nw = wid & 3;                 // 2 x 4 warp grid
    const int rowBase = blockIdx.y * 128, colBase = blockIdx.x * 128;

    const __nv_bfloat16* aHi = aP + (size_t)rowBase * DMODEL;
    const __nv_bfloat16* aLo = aHi + (size_t)M * DMODEL;
    const __nv_bfloat16* bHi = wP + (size_t)colBase * DMODEL;
    const __nv_bfloat16* bLo = bHi + (size_t)DMODEL * DMODEL;

    // load mapping: 512 16B-chunks per plane, 2 per thread: chunk = tid + 256*i
    // row = chunk/4, c = chunk%4 -> gmem 64B per 4 threads, smem row*80 + c*16
    const int r0 = tid >> 2, c0 = (tid & 3) << 4;          // i=0: rows 0..63
    const int r1 = r0 + 64;                                // i=1: rows 64..127

    auto load_stage = [&](int kt, int s) {
        const uint32_t sb = sbase + s * STAGE;
        const size_t g0 = (size_t)r0 * DMODEL + kt * 32;   // elements
        const size_t g1 = (size_t)r1 * DMODEL + kt * 32;
        const uint32_t s0 = r0 * SROW + c0, s1 = r1 * SROW + c0;
        cp16(sb + 0 * PLANE + s0, (const char*)(aHi + g0) + c0);
        cp16(sb + 0 * PLANE + s1, (const char*)(aHi + g1) + c0);
        cp16(sb + 1 * PLANE + s0, (const char*)(aLo + g0) + c0);
        cp16(sb + 1 * PLANE + s1, (const char*)(aLo + g1) + c0);
        cp16(sb + 2 * PLANE + s0, (const char*)(bHi + g0) + c0);
        cp16(sb + 2 * PLANE + s1, (const char*)(bHi + g1) + c0);
        cp16(sb + 3 * PLANE + s0, (const char*)(bLo + g0) + c0);
        cp16(sb + 3 * PLANE + s1, (const char*)(bLo + g1) + c0);
    };

    float acc[4][4][4] = {};                               // [mi][n8][reg]
    const int lr = lane & 15, lc = lane >> 4;

    load_stage(0, 0);
    cp_commit();

    const int NIT = DMODEL / 32;                           // 32
    for (int kt = 0; kt < NIT; kt++) {
        if (kt + 1 < NIT) load_stage(kt + 1, (kt + 1) & 1);
        cp_commit();
        cp_wait<1>();
        __syncthreads();

        const uint32_t sb = sbase + (kt & 1) * STAGE;
        #pragma unroll
        for (int kk = 0; kk < 2; kk++) {
            uint32_t ah[4][4], al[4][4], bh[2][4], bl[2][4];
            #pragma unroll
            for (int mi = 0; mi < 4; mi++) {
                uint32_t ra = sb + (mw * 64 + mi * 16 + lr) * SROW + kk * 32 + lc * 16;
                ldm_x4(ah[mi], ra);
                ldm_x4(al[mi], ra + PLANE);
            }
            #pragma unroll
            for (int ni = 0; ni < 2; ni++) {
                uint32_t rb = sb + 2 * PLANE + (nw * 32 + ni * 16 + lr) * SROW + kk * 32 + lc * 16;
                ldm_x4(bh[ni], rb);
                ldm_x4(bl[ni], rb + PLANE);
            }
            #pragma unroll
            for (int mi = 0; mi < 4; mi++) {
                #pragma unroll
                for (int n8 = 0; n8 < 4; n8++) {
                    const int ni = n8 >> 1, hf = n8 & 1;
                    mma16816(acc[mi][n8], ah[mi], bh[ni][hf], bh[ni][hf + 2]);
                    mma16816(acc[mi][n8], al[mi], bh[ni][hf], bh[ni][hf + 2]);
                    mma16816(acc[mi][n8], ah[mi], bl[ni][hf], bl[ni][hf + 2]);
                }
            }
        }
        __syncthreads();
    }

    // epilogue: d0/d1 -> (row lane/4, col 2*(lane%4)+{0,1}); d2/d3 -> row+8
    const int wr = rowBase + mw * 64, wc = colBase + nw * 32;
    #pragma unroll
    for (int mi = 0; mi < 4; mi++) {
        #pragma unroll
        for (int n8 = 0; n8 < 4; n8++) {
            const int col = wc + n8 * 8 + (lane & 3) * 2;
            const float b0 = bias[col], b1 = bias[col + 1];
            #pragma unroll
            for (int h = 0; h < 2; h++) {
                const int row = wr + mi * 16 + (lane >> 2) + 8 * h;
                float2 o;
                o.x = (acc[mi][n8][2 * h + 0] + b0) * scale;
                o.y = (acc[mi][n8][2 * h + 1] + b1) * scale;
                if (split) {
                    int bb = row >> 11, ss = row & 2047;
                    int hh = col >> 6, dd = col & 63;
                    *(float2*)&C[((size_t)(bb * NHEADS + hh) * S_LEN + ss) * DK + dd] = o;
                } else {
                    *(float2*)&C[(size_t)row * DMODEL + col] = o;
                }
            }
        }
    }
}

// ============================================================================
// Flash attention (unchanged fp32, verified round-1)
// ============================================================================
__device__ __forceinline__ int swz(int major, int minor) {
    return major * 64 + ((((minor >> 2) ^ (major & 15)) << 2) | (minor & 3));
}
__device__ __forceinline__ int swz4(int major, int minor4) {
    return major * 64 + ((minor4 ^ (major & 15)) << 2);
}

__global__ __launch_bounds__(256) void attn_kernel()
{
    __shared__ float qs [4096];
    __shared__ float kvs[4096];
    __shared__ float ps [4096];

    const int tid = threadIdx.x;
    const int tx = tid & 15, ty = tid >> 4;
    const int q0 = blockIdx.x * 64;
    const int h  = blockIdx.y;
    const int b  = blockIdx.z;

    const float* qg = g_q + ((size_t)(b * NHEADS + h) * S_LEN) * DK;
    const float* kg = g_k + ((size_t)(b * NHEADS + h) * S_LEN) * DK;
    const float* vg = g_v + ((size_t)(b * NHEADS + h) * S_LEN) * DK;

    #pragma unroll
    for (int rr = 0; rr < 4; rr++) {
        int r = ty + 16 * rr;
        float4 v = *(const float4*)&qg[(q0 + r) * DK + 4 * tx];
        qs[swz(4*tx + 0, r)] = v.x;
        qs[swz(4*tx + 1, r)] = v.y;
        qs[swz(4*tx + 2, r)] = v.z;
        qs[swz(4*tx + 3, r)] = v.w;
    }

    float o[4][4] = {};
    float m[4] = {-1e30f, -1e30f, -1e30f, -1e30f};
    float l[4] = {};

    for (int kt = 0; kt < S_LEN / 64; kt++) {
        #pragma unroll
        for (int rr = 0; rr < 4; rr++) {
            int r = ty + 16 * rr;
            float4 v = *(const float4*)&kg[(kt * 64 + r) * DK + 4 * tx];
            kvs[swz(4*tx + 0, r)] = v.x;
            kvs[swz(4*tx + 1, r)] = v.y;
            kvs[swz(4*tx + 2, r)] = v.z;
            kvs[swz(4*tx + 3, r)] = v.w;
        }
        __syncthreads();

        float s[4][4] = {};
        #pragma unroll
        for (int d = 0; d < 64; d++) {
            float4 qf = *(const float4*)&qs [swz4(d, ty)];
            float4 kf = *(const float4*)&kvs[swz4(d, tx)];
            s[0][0] += qf.x*kf.x; s[0][1] += qf.x*kf.y; s[0][2] += qf.x*kf.z; s[0][3] += qf.x*kf.w;
            s[1][0] += qf.y*kf.x; s[1][1] += qf.y*kf.y; s[1][2] += qf.y*kf.z; s[1][3] += qf.y*kf.w;
            s[2][0] += qf.z*kf.x; s[2][1] += qf.z*kf.y; s[2][2] += qf.z*kf.z; s[2][3] += qf.z*kf.w;
            s[3][0] += qf.w*kf.x; s[3][1] += qf.w*kf.y; s[3][2] += qf.w*kf.z; s[3][3] += qf.w*kf.w;
        }

        #pragma unroll
        for (int i = 0; i < 4; i++) {
            float tm = fmaxf(fmaxf(s[i][0], s[i][1]), fmaxf(s[i][2], s[i][3]));
            #pragma unroll
            for (int off = 8; off; off >>= 1)
                tm = fmaxf(tm, __shfl_xor_sync(0xffffffffu, tm, off));
            float mn = fmaxf(m[i], tm);
            float corr = __expf(m[i] - mn);
            float ls = 0.f;
            #pragma unroll
            for (int j = 0; j < 4; j++) { s[i][j] = __expf(s[i][j] - mn); ls += s[i][j]; }
            #pragma unroll
            for (int off = 8; off; off >>= 1)
                ls += __shfl_xor_sync(0xffffffffu, ls, off);
            l[i] = l[i] * corr + ls;
            m[i] = mn;
            #pragma unroll
            for (int j = 0; j < 4; j++) o[i][j] *= corr;
            #pragma unroll
            for (int j = 0; j < 4; j++) ps[swz(4*tx + j, 4*ty + i)] = s[i][j];
        }
        __syncthreads();

        #pragma unroll
        for (int rr = 0; rr < 4; rr++) {
            int r = ty + 16 * rr;
            float4 v = *(const float4*)&vg[(kt * 64 + r) * DK + 4 * tx];
            *(float4*)&kvs[swz4(r, tx)] = v;
        }
        __syncthreads();

        #pragma unroll
        for (int c = 0; c < 64; c++) {
            float4 pf = *(const float4*)&ps [swz4(c, ty)];
            float4 vf = *(const float4*)&kvs[swz4(c, tx)];
            o[0][0] += pf.x*vf.x; o[0][1] += pf.x*vf.y; o[0][2] += pf.x*vf.z; o[0][3] += pf.x*vf.w;
            o[1][0] += pf.y*vf.x; o[1][1] += pf.y*vf.y; o[1][2] += pf.y*vf.z; o[1][3] += pf.y*vf.w;
            o[2][0] += pf.z*vf.x; o[2][1] += pf.z*vf.y; o[2][2] += pf.z*vf.z; o[2][3] += pf.z*vf.w;
            o[3][0] += pf.w*vf.x; o[3][1] += pf.w*vf.y; o[3][2] += pf.w*vf.z; o[3][3] += pf.w*vf.w;
        }
        __syncthreads();
    }

    float* og = g_attn + (size_t)b * S_LEN * DMODEL + h * DK;
    #pragma unroll
    for (int i = 0; i < 4; i++) {
        float inv = 1.0f / l[i];
        float4 w;
        w.x = o[i][0] * inv; w.y = o[i][1] * inv; w.z = o[i][2] * inv; w.w = o[i][3] * inv;
        *(float4*)&og[(size_t)(q0 + 4*ty + i) * DMODEL + 4 * tx] = w;
    }
}

// ============================================================================
extern "C" void kernel_launch(void* const* d_in, const int* in_sizes, int n_in,
                              void* d_out, int out_size)
{
    const float* Q  = (const float*)d_in[0];
    const float* K_ = (const float*)d_in[1];
    const float* V  = (const float*)d_in[2];
    const float* Wq = (const float*)d_in[3];
    const float* bq = (const float*)d_in[4];
    const float* Wk = (const float*)d_in[5];
    const float* bk = (const float*)d_in[6];
    const float* Wv = (const float*)d_in[7];
    const float* bv = (const float*)d_in[8];
    const float* Wo = (const float*)d_in[9];
    const float* bo = (const float*)d_in[10];

    int B = in_sizes[0] / (S_LEN * DMODEL);
    if (B > MAXB) B = MAXB;
    const int M = B * S_LEN;

    float *pq, *pk, *pv, *pa;
    __nv_bfloat16 *aP, *wP;
    cudaGetSymbolAddress((void**)&pq, g_q);
    cudaGetSymbolAddress((void**)&pk, g_k);
    cudaGetSymbolAddress((void**)&pv, g_v);
    cudaGetSymbolAddress((void**)&pa, g_attn);
    cudaGetSymbolAddress((void**)&aP, g_a16);
    cudaGetSymbolAddress((void**)&wP, g_w16);
    const size_t WSZ = 2ull * DMODEL * DMODEL;

    cudaFuncSetAttribute(gemm_mma, cudaFuncAttributeMaxDynamicSharedMemorySize, GEMM_SMEM);

    conv_split_w<<<1024, 256>>>(Wq, wP + 0 * WSZ);
    conv_split_w<<<1024, 256>>>(Wk, wP + 1 * WSZ);
    conv_split_w<<<1024, 256>>>(Wv, wP + 2 * WSZ);
    conv_split_w<<<1024, 256>>>(Wo, wP + 3 * WSZ);

    dim3 gg(DMODEL / 128, M / 128);

    conv_split_a<<<M, 256>>>(Q, aP, M);
    gemm_mma<<<gg, 256, GEMM_SMEM>>>(aP, wP + 0 * WSZ, bq, pq, M, 1, 0.125f);
    conv_split_a<<<M, 256>>>(K_, aP, M);
    gemm_mma<<<gg, 256, GEMM_SMEM>>>(aP, wP + 1 * WSZ, bk, pk, M, 1, 1.0f);
    conv_split_a<<<M, 256>>>(V, aP, M);
    gemm_mma<<<gg, 256, GEMM_SMEM>>>(aP, wP + 2 * WSZ, bv, pv, M, 1, 1.0f);

    attn_kernel<<<dim3(S_LEN / 64, NHEADS, B), 256>>>();

    conv_split_a<<<M, 256>>>(pa, aP, M);
    gemm_mma<<<gg, 256, GEMM_SMEM>>>(aP, wP + 3 * WSZ, bo, (float*)d_out, M, 0, 1.0f);
}

// round 4
// speedup vs baseline: 2.3340x; 1.7125x over previous
#include <cuda_runtime.h>
#include <cuda_bf16.h>
#include <math.h>
#include <stdint.h>

#define S_LEN  2048
#define DMODEL 1024
#define NHEADS 16
#define DK     64
#define MAXB   2
#define MMAX   (MAXB * S_LEN)      // 4096

// ---- scratch (device globals: allocation-free) ----
__device__ float g_attn[MAXB * S_LEN * DMODEL];
// bf16 hi/lo planes for GEMM A-input and weights
__device__ __align__(16) __nv_bfloat16 g_a16[2ull * MMAX * DMODEL];            // 16 MB
__device__ __align__(16) __nv_bfloat16 g_w16[4][2ull * DMODEL * DMODEL];       // 4 x 4 MB
// bf16 hi/lo planes for q/k/v, layout (B,H,S,DK)
__device__ __align__(16) __nv_bfloat16 g_qh[MMAX * DMODEL], g_ql[MMAX * DMODEL];
__device__ __align__(16) __nv_bfloat16 g_kh[MMAX * DMODEL], g_kl[MMAX * DMODEL];
__device__ __align__(16) __nv_bfloat16 g_vh[MMAX * DMODEL], g_vl[MMAX * DMODEL];

// ============================================================================
// helpers
// ============================================================================
__device__ __forceinline__ uint32_t smem_u32(const void* p) {
    uint32_t r;
    asm("{ .reg .u64 t; cvta.to.shared.u64 t, %1; cvt.u32.u64 %0, t; }" : "=r"(r) : "l"(p));
    return r;
}
__device__ __forceinline__ void split2(float v, __nv_bfloat16& h, __nv_bfloat16& l) {
    h = __float2bfloat16(v);
    l = __float2bfloat16(v - __bfloat162float(h));
}
__device__ __forceinline__ uint32_t pack2(__nv_bfloat16 a, __nv_bfloat16 b) {
    __nv_bfloat162 t = __halves2bfloat162(a, b);
    return *reinterpret_cast<uint32_t*>(&t);
}
__device__ __forceinline__ void cp16(uint32_t s, const void* g) {
    asm volatile("cp.async.cg.shared.global [%0], [%1], 16;" :: "r"(s), "l"(g));
}
__device__ __forceinline__ void cp_commit() {
    asm volatile("cp.async.commit_group;");
}
template <int N> __device__ __forceinline__ void cp_wait() {
    asm volatile("cp.async.wait_group %0;" :: "n"(N));
}
__device__ __forceinline__ void ldm_x4(uint32_t* r, uint32_t a) {
    asm volatile("ldmatrix.sync.aligned.m8n8.x4.shared.b16 {%0,%1,%2,%3}, [%4];"
                 : "=r"(r[0]), "=r"(r[1]), "=r"(r[2]), "=r"(r[3]) : "r"(a));
}
__device__ __forceinline__ void ldm_x4t(uint32_t* r, uint32_t a) {
    asm volatile("ldmatrix.sync.aligned.m8n8.x4.trans.shared.b16 {%0,%1,%2,%3}, [%4];"
                 : "=r"(r[0]), "=r"(r[1]), "=r"(r[2]), "=r"(r[3]) : "r"(a));
}
__device__ __forceinline__ void mma16816(float* d, const uint32_t* a, uint32_t b0, uint32_t b1) {
    asm volatile(
        "mma.sync.aligned.m16n8k16.row.col.f32.bf16.bf16.f32 "
        "{%0,%1,%2,%3}, {%4,%5,%6,%7}, {%8,%9}, {%0,%1,%2,%3};"
        : "+f"(d[0]), "+f"(d[1]), "+f"(d[2]), "+f"(d[3])
        : "r"(a[0]), "r"(a[1]), "r"(a[2]), "r"(a[3]), "r"(b0), "r"(b1));
}

// ============================================================================
// conversion: A[M,1024] fp32 -> hi/lo bf16 planes, row-major
// ============================================================================
__global__ __launch_bounds__(256) void conv_split_a(
    const float* __restrict__ A, __nv_bfloat16* __restrict__ dst, int M)
{
    int idx = blockIdx.x * 256 + threadIdx.x;
    if (idx >= M * 256) return;
    int row = idx >> 8, kg = idx & 255;
    float4 v = *(const float4*)(A + (size_t)row * DMODEL + kg * 4);
    __nv_bfloat16 h0, h1, h2, h3, l0, l1, l2, l3;
    split2(v.x, h0, l0); split2(v.y, h1, l1); split2(v.z, h2, l2); split2(v.w, h3, l3);
    size_t off = (size_t)row * DMODEL + kg * 4;
    size_t loPl = (size_t)M * DMODEL;
    *(uint2*)(dst + off)        = make_uint2(pack2(h0, h1), pack2(h2, h3));
    *(uint2*)(dst + loPl + off) = make_uint2(pack2(l0, l1), pack2(l2, l3));
}

__global__ __launch_bounds__(256) void conv_split_w(
    const float* __restrict__ W, __nv_bfloat16* __restrict__ dst)
{
    int idx = blockIdx.x * 256 + threadIdx.x;
    int kg = idx >> 10, n = idx & 1023;
    int k0 = kg * 4;
    float a0 = W[(size_t)(k0 + 0) * DMODEL + n];
    float a1 = W[(size_t)(k0 + 1) * DMODEL + n];
    float a2 = W[(size_t)(k0 + 2) * DMODEL + n];
    float a3 = W[(size_t)(k0 + 3) * DMODEL + n];
    __nv_bfloat16 h0, h1, h2, h3, l0, l1, l2, l3;
    split2(a0, h0, l0); split2(a1, h1, l1); split2(a2, h2, l2); split2(a3, h3, l3);
    size_t off = (size_t)n * DMODEL + k0;
    size_t loPl = (size_t)DMODEL * DMODEL;
    *(uint2*)(dst + off)        = make_uint2(pack2(h0, h1), pack2(h2, h3));
    *(uint2*)(dst + loPl + off) = make_uint2(pack2(l0, l1), pack2(l2, l3));
}

// ============================================================================
// mma.sync bf16x3 GEMM: C = (A*W + bias) * scale
// mode 0: fp32 C row-major [M][1024]
// mode 1: split hi/lo bf16 to (B,H,S,DK) planes outH / outL
// ============================================================================
#define SROW   80
#define PLANE  (128 * SROW)
#define STAGE  (4 * PLANE)
#define GEMM_SMEM (2 * STAGE)

__global__ __launch_bounds__(256) void gemm_mma(
    const __nv_bfloat16* __restrict__ aP, const __nv_bfloat16* __restrict__ wP,
    const float* __restrict__ bias, float* __restrict__ C,
    __nv_bfloat16* __restrict__ outH, __nv_bfloat16* __restrict__ outL,
    int M, int mode, float scale)
{
    extern __shared__ unsigned char dyn[];
    const uint32_t sbase = smem_u32(dyn);

    const int tid = threadIdx.x, lane = tid & 31, wid = tid >> 5;
    const int mw = wid >> 2, nw = wid & 3;
    const int rowBase = blockIdx.y * 128, colBase = blockIdx.x * 128;

    const __nv_bfloat16* aHi = aP + (size_t)rowBase * DMODEL;
    const __nv_bfloat16* aLo = aHi + (size_t)M * DMODEL;
    const __nv_bfloat16* bHi = wP + (size_t)colBase * DMODEL;
    const __nv_bfloat16* bLo = bHi + (size_t)DMODEL * DMODEL;

    const int r0 = tid >> 2, c0 = (tid & 3) << 4;
    const int r1 = r0 + 64;

    auto load_stage = [&](int kt, int s) {
        const uint32_t sb = sbase + s * STAGE;
        const size_t g0 = (size_t)r0 * DMODEL + kt * 32;
        const size_t g1 = (size_t)r1 * DMODEL + kt * 32;
        const uint32_t s0 = r0 * SROW + c0, s1 = r1 * SROW + c0;
        cp16(sb + 0 * PLANE + s0, (const char*)(aHi + g0) + c0);
        cp16(sb + 0 * PLANE + s1, (const char*)(aHi + g1) + c0);
        cp16(sb + 1 * PLANE + s0, (const char*)(aLo + g0) + c0);
        cp16(sb + 1 * PLANE + s1, (const char*)(aLo + g1) + c0);
        cp16(sb + 2 * PLANE + s0, (const char*)(bHi + g0) + c0);
        cp16(sb + 2 * PLANE + s1, (const char*)(bHi + g1) + c0);
        cp16(sb + 3 * PLANE + s0, (const char*)(bLo + g0) + c0);
        cp16(sb + 3 * PLANE + s1, (const char*)(bLo + g1) + c0);
    };

    float acc[4][4][4] = {};
    const int lr = lane & 15, lc = lane >> 4;

    load_stage(0, 0);
    cp_commit();

    const int NIT = DMODEL / 32;
    for (int kt = 0; kt < NIT; kt++) {
        if (kt + 1 < NIT) load_stage(kt + 1, (kt + 1) & 1);
        cp_commit();
        cp_wait<1>();
        __syncthreads();

        const uint32_t sb = sbase + (kt & 1) * STAGE;
        #pragma unroll
        for (int kk = 0; kk < 2; kk++) {
            uint32_t ah[4][4], al[4][4], bh[2][4], bl[2][4];
            #pragma unroll
            for (int mi = 0; mi < 4; mi++) {
                uint32_t ra = sb + (mw * 64 + mi * 16 + lr) * SROW + kk * 32 + lc * 16;
                ldm_x4(ah[mi], ra);
                ldm_x4(al[mi], ra + PLANE);
            }
            #pragma unroll
            for (int ni = 0; ni < 2; ni++) {
                uint32_t rb = sb + 2 * PLANE + (nw * 32 + ni * 16 + lr) * SROW + kk * 32 + lc * 16;
                ldm_x4(bh[ni], rb);
                ldm_x4(bl[ni], rb + PLANE);
            }
            #pragma unroll
            for (int mi = 0; mi < 4; mi++) {
                #pragma unroll
                for (int n8 = 0; n8 < 4; n8++) {
                    const int ni = n8 >> 1, hf = n8 & 1;
                    mma16816(acc[mi][n8], ah[mi], bh[ni][hf], bh[ni][hf + 2]);
                    mma16816(acc[mi][n8], al[mi], bh[ni][hf], bh[ni][hf + 2]);
                    mma16816(acc[mi][n8], ah[mi], bl[ni][hf], bl[ni][hf + 2]);
                }
            }
        }
        __syncthreads();
    }

    const int wr = rowBase + mw * 64, wc = colBase + nw * 32;
    #pragma unroll
    for (int mi = 0; mi < 4; mi++) {
        #pragma unroll
        for (int n8 = 0; n8 < 4; n8++) {
            const int col = wc + n8 * 8 + (lane & 3) * 2;
            const float b0 = bias[col], b1 = bias[col + 1];
            #pragma unroll
            for (int h = 0; h < 2; h++) {
                const int row = wr + mi * 16 + (lane >> 2) + 8 * h;
                float ox = (acc[mi][n8][2 * h + 0] + b0) * scale;
                float oy = (acc[mi][n8][2 * h + 1] + b1) * scale;
                if (mode) {
                    int bb = row >> 11, ss = row & 2047;
                    int hh = col >> 6, dd = col & 63;
                    size_t e = ((size_t)(bb * NHEADS + hh) * S_LEN + ss) * DK + dd;
                    __nv_bfloat16 hx, lx, hy, ly;
                    split2(ox, hx, lx); split2(oy, hy, ly);
                    *(uint32_t*)(outH + e) = pack2(hx, hy);
                    *(uint32_t*)(outL + e) = pack2(lx, ly);
                } else {
                    float2 o; o.x = ox; o.y = oy;
                    *(float2*)&C[(size_t)row * DMODEL + col] = o;
                }
            }
        }
    }
}

// ============================================================================
// FA2-style attention with mma.sync bf16x3.
// CTA: 128 q-rows x (head, batch). 8 warps, each 16 q-rows. kv tile 64.
// ============================================================================
#define AT_SROW  144                  // 64 bf16 = 128B + 16 pad
#define AT_PLANE (64 * AT_SROW)       // 9216
#define AT_STAGE (4 * AT_PLANE)       // Kh Kl Vh Vl = 36864
#define ATT_SMEM (2 * AT_STAGE)       // 73728

__global__ __launch_bounds__(256) void attn_mma(
    const __nv_bfloat16* __restrict__ qhG, const __nv_bfloat16* __restrict__ qlG,
    const __nv_bfloat16* __restrict__ khG, const __nv_bfloat16* __restrict__ klG,
    const __nv_bfloat16* __restrict__ vhG, const __nv_bfloat16* __restrict__ vlG,
    float* __restrict__ out)
{
    extern __shared__ unsigned char dyn[];
    const uint32_t sb = smem_u32(dyn);
    const int tid = threadIdx.x, lane = tid & 31, wid = tid >> 5;
    const int q0 = blockIdx.x * 128, h = blockIdx.y, b = blockIdx.z;
    const size_t hb = (size_t)(b * NHEADS + h) * S_LEN * DK;

    const char* qhB = (const char*)(qhG + hb);
    const char* qlB = (const char*)(qlG + hb);
    const char* khB = (const char*)(khG + hb);
    const char* klB = (const char*)(klG + hb);
    const char* vhB = (const char*)(vhG + hb);
    const char* vlB = (const char*)(vlG + hb);

    // ---- stage Q tile (hi/lo) through smem, ldmatrix to registers ----
    #pragma unroll
    for (int i = 0; i < 8; i++) {
        int cid = tid + 256 * i;               // 2048 chunks of 16B
        int pl = cid >> 10;                    // 0 hi, 1 lo
        int r  = (cid >> 3) & 127;
        int c  = (cid & 7) * 16;
        const char* g = (pl ? qlB : qhB) + (size_t)(q0 + r) * (DK * 2) + c;
        cp16(sb + pl * (128 * AT_SROW) + r * AT_SROW + c, g);
    }
    cp_commit(); cp_wait<0>(); __syncthreads();

    const int lr = lane & 15, lc = lane >> 4;
    uint32_t qfh[4][4], qfl[4][4];
    #pragma unroll
    for (int ks = 0; ks < 4; ks++) {
        uint32_t a = sb + (wid * 16 + lr) * AT_SROW + ks * 32 + lc * 16;
        ldm_x4(qfh[ks], a);
        ldm_x4(qfl[ks], a + 128 * AT_SROW);
    }
    __syncthreads();

    float o[8][4] = {};
    float m0 = -1e30f, m1 = -1e30f, l0 = 0.f, l1 = 0.f;

    auto load_kv = [&](int t, int s) {
        const uint32_t st = sb + s * AT_STAGE;
        #pragma unroll
        for (int i = 0; i < 8; i++) {
            int cid = tid + 256 * i;           // 2048 chunks
            int pl = cid >> 9;                 // 0 kh, 1 kl, 2 vh, 3 vl
            int r  = (cid >> 3) & 63;
            int c  = (cid & 7) * 16;
            const char* g = (pl == 0) ? khB : (pl == 1) ? klB : (pl == 2) ? vhB : vlB;
            g += (size_t)(t * 64 + r) * (DK * 2) + c;
            cp16(st + pl * AT_PLANE + r * AT_SROW + c, g);
        }
    };

    load_kv(0, 0);
    cp_commit();

    const int NT = S_LEN / 64;
    for (int t = 0; t < NT; t++) {
        if (t + 1 < NT) load_kv(t + 1, (t + 1) & 1);
        cp_commit();
        cp_wait<1>();
        __syncthreads();
        const uint32_t st = sb + (t & 1) * AT_STAGE;

        // ---- S = Q K^T (bf16x3) ----
        float s[8][4] = {};
        #pragma unroll
        for (int g = 0; g < 4; g++) {
            #pragma unroll
            for (int ks = 0; ks < 4; ks++) {
                uint32_t kfh[4], kfl[4];
                uint32_t a = st + (g * 16 + lr) * AT_SROW + ks * 32 + lc * 16;
                ldm_x4(kfh, a);
                ldm_x4(kfl, a + AT_PLANE);
                #pragma unroll
                for (int hf = 0; hf < 2; hf++) {
                    mma16816(s[2 * g + hf], qfh[ks], kfh[hf], kfh[hf + 2]);
                    mma16816(s[2 * g + hf], qfl[ks], kfh[hf], kfh[hf + 2]);
                    mma16816(s[2 * g + hf], qfh[ks], kfl[hf], kfl[hf + 2]);
                }
            }
        }

        // ---- online softmax (rows r0 = lane/4, r1 = r0+8) ----
        float mx0 = -1e30f, mx1 = -1e30f;
        #pragma unroll
        for (int j = 0; j < 8; j++) {
            mx0 = fmaxf(mx0, fmaxf(s[j][0], s[j][1]));
            mx1 = fmaxf(mx1, fmaxf(s[j][2], s[j][3]));
        }
        mx0 = fmaxf(mx0, __shfl_xor_sync(0xffffffffu, mx0, 1));
        mx0 = fmaxf(mx0, __shfl_xor_sync(0xffffffffu, mx0, 2));
        mx1 = fmaxf(mx1, __shfl_xor_sync(0xffffffffu, mx1, 1));
        mx1 = fmaxf(mx1, __shfl_xor_sync(0xffffffffu, mx1, 2));
        const float mn0 = fmaxf(m0, mx0), mn1 = fmaxf(m1, mx1);
        const float c0 = __expf(m0 - mn0), c1 = __expf(m1 - mn1);
        float ls0 = 0.f, ls1 = 0.f;
        #pragma unroll
        for (int j = 0; j < 8; j++) {
            s[j][0] = __expf(s[j][0] - mn0);
            s[j][1] = __expf(s[j][1] - mn0);
            s[j][2] = __expf(s[j][2] - mn1);
            s[j][3] = __expf(s[j][3] - mn1);
            ls0 += s[j][0] + s[j][1];
            ls1 += s[j][2] + s[j][3];
        }
        ls0 += __shfl_xor_sync(0xffffffffu, ls0, 1);
        ls0 += __shfl_xor_sync(0xffffffffu, ls0, 2);
        ls1 += __shfl_xor_sync(0xffffffffu, ls1, 1);
        ls1 += __shfl_xor_sync(0xffffffffu, ls1, 2);
        l0 = l0 * c0 + ls0;  l1 = l1 * c1 + ls1;
        m0 = mn0;  m1 = mn1;
        #pragma unroll
        for (int j = 0; j < 8; j++) {
            o[j][0] *= c0; o[j][1] *= c0;
            o[j][2] *= c1; o[j][3] *= c1;
        }

        // ---- P -> A fragments (hi/lo), in registers ----
        uint32_t ph[4][4], pq[4][4];
        #pragma unroll
        for (int k = 0; k < 4; k++) {
            #pragma unroll
            for (int u = 0; u < 4; u++) {
                const int jt = 2 * k + (u >> 1);
                const int e  = (u & 1) * 2;
                __nv_bfloat16 hx, lx, hy, ly;
                split2(s[jt][e + 0], hx, lx);
                split2(s[jt][e + 1], hy, ly);
                // u: 0 -> (row r0, k0-7) ; 1 -> (r1, k0-7) ; 2 -> (r0, k8-15) ; 3 -> (r1, k8-15)
                const int ridx = (u == 0) ? 0 : (u == 1) ? 1 : (u == 2) ? 2 : 3;
                ph[k][ridx] = pack2(hx, hy);
                pq[k][ridx] = pack2(lx, ly);
            }
        }
        // fix ordering: a0=(r0,k0-7) from tile 2k regs {0,1}; a1=(r1,k0-7) from tile 2k regs {2,3};
        // a2=(r0,k8-15) tile 2k+1 {0,1}; a3=(r1,k8-15) tile 2k+1 {2,3}
        // (mapping above: u0->tile2k e0 = a0 ✓, u1->tile2k e2 = a1 ✓, u2->tile2k+1 e0 = a2 ✓, u3->tile2k+1 e2 = a3 ✓)

        // ---- O += P V (bf16x3), V via ldmatrix.trans ----
        #pragma unroll
        for (int d = 0; d < 4; d++) {
            #pragma unroll
            for (int k = 0; k < 4; k++) {
                uint32_t vfh[4], vfl[4];
                uint32_t a = st + 2 * AT_PLANE + (k * 16 + lr) * AT_SROW + d * 32 + lc * 16;
                ldm_x4t(vfh, a);
                ldm_x4t(vfl, a + AT_PLANE);
                mma16816(o[2 * d + 0], ph[k], vfh[0], vfh[1]);
                mma16816(o[2 * d + 0], pq[k], vfh[0], vfh[1]);
                mma16816(o[2 * d + 0], ph[k], vfl[0], vfl[1]);
                mma16816(o[2 * d + 1], ph[k], vfh[2], vfh[3]);
                mma16816(o[2 * d + 1], pq[k], vfh[2], vfh[3]);
                mma16816(o[2 * d + 1], ph[k], vfl[2], vfl[3]);
            }
        }
        __syncthreads();
    }

    // ---- epilogue: /l, write fp32 combined (B,S,H*Dk) ----
    const float inv0 = 1.0f / l0, inv1 = 1.0f / l1;
    const int row0 = q0 + wid * 16 + (lane >> 2);
    const int cb = (lane & 3) * 2;
    #pragma unroll
    for (int j = 0; j < 8; j++) {
        const int col = h * DK + j * 8 + cb;
        float2 w0; w0.x = o[j][0] * inv0; w0.y = o[j][1] * inv0;
        float2 w1; w1.x = o[j][2] * inv1; w1.y = o[j][3] * inv1;
        *(float2*)&out[((size_t)b * S_LEN + row0) * DMODEL + col] = w0;
        *(float2*)&out[((size_t)b * S_LEN + row0 + 8) * DMODEL + col] = w1;
    }
}

// ============================================================================
extern "C" void kernel_launch(void* const* d_in, const int* in_sizes, int n_in,
                              void* d_out, int out_size)
{
    const float* Q  = (const float*)d_in[0];
    const float* K_ = (const float*)d_in[1];
    const float* V  = (const float*)d_in[2];
    const float* Wq = (const float*)d_in[3];
    const float* bq = (const float*)d_in[4];
    const float* Wk = (const float*)d_in[5];
    const float* bk = (const float*)d_in[6];
    const float* Wv = (const float*)d_in[7];
    const float* bv = (const float*)d_in[8];
    const float* Wo = (const float*)d_in[9];
    const float* bo = (const float*)d_in[10];

    int B = in_sizes[0] / (S_LEN * DMODEL);
    if (B > MAXB) B = MAXB;
    const int M = B * S_LEN;

    float* pa;
    __nv_bfloat16 *aP, *wP, *qh, *ql, *kh, *kl, *vh, *vl;
    cudaGetSymbolAddress((void**)&pa, g_attn);
    cudaGetSymbolAddress((void**)&aP, g_a16);
    cudaGetSymbolAddress((void**)&wP, g_w16);
    cudaGetSymbolAddress((void**)&qh, g_qh);
    cudaGetSymbolAddress((void**)&ql, g_ql);
    cudaGetSymbolAddress((void**)&kh, g_kh);
    cudaGetSymbolAddress((void**)&kl, g_kl);
    cudaGetSymbolAddress((void**)&vh, g_vh);
    cudaGetSymbolAddress((void**)&vl, g_vl);
    const size_t WSZ = 2ull * DMODEL * DMODEL;

    cudaFuncSetAttribute(gemm_mma, cudaFuncAttributeMaxDynamicSharedMemorySize, GEMM_SMEM);
    cudaFuncSetAttribute(attn_mma, cudaFuncAttributeMaxDynamicSharedMemorySize, ATT_SMEM);

    conv_split_w<<<1024, 256>>>(Wq, wP + 0 * WSZ);
    conv_split_w<<<1024, 256>>>(Wk, wP + 1 * WSZ);
    conv_split_w<<<1024, 256>>>(Wv, wP + 2 * WSZ);
    conv_split_w<<<1024, 256>>>(Wo, wP + 3 * WSZ);

    dim3 gg(DMODEL / 128, M / 128);

    conv_split_a<<<M, 256>>>(Q, aP, M);
    gemm_mma<<<gg, 256, GEMM_SMEM>>>(aP, wP + 0 * WSZ, bq, nullptr, qh, ql, M, 1, 0.125f);
    conv_split_a<<<M, 256>>>(K_, aP, M);
    gemm_mma<<<gg, 256, GEMM_SMEM>>>(aP, wP + 1 * WSZ, bk, nullptr, kh, kl, M, 1, 1.0f);
    conv_split_a<<<M, 256>>>(V, aP, M);
    gemm_mma<<<gg, 256, GEMM_SMEM>>>(aP, wP + 2 * WSZ, bv, nullptr, vh, vl, M, 1, 1.0f);

    attn_mma<<<dim3(S_LEN / 128, NHEADS, B), 256, ATT_SMEM>>>(qh, ql, kh, kl, vh, vl, pa);

    conv_split_a<<<M, 256>>>(pa, aP, M);
    gemm_mma<<<gg, 256, GEMM_SMEM>>>(aP, wP + 3 * WSZ, bo, (float*)d_out, nullptr, nullptr, M, 0, 1.0f);
}

// round 5
// speedup vs baseline: 2.4572x; 1.0528x over previous
#include <cuda_runtime.h>
#include <cuda_bf16.h>
#include <math.h>
#include <stdint.h>

#define S_LEN  2048
#define DMODEL 1024
#define NHEADS 16
#define DK     64
#define MAXB   2
#define MMAX   (MAXB * S_LEN)      // 4096

// ---- scratch (device globals: allocation-free) ----
// bf16 hi/lo planes for GEMM A-input and weights
__device__ __align__(16) __nv_bfloat16 g_a16[2ull * MMAX * DMODEL];            // 16 MB
__device__ __align__(16) __nv_bfloat16 g_w16[4][2ull * DMODEL * DMODEL];       // 4 x 4 MB
// bf16 hi/lo planes for q/k/v, layout (B,H,S,DK)
__device__ __align__(16) __nv_bfloat16 g_qh[MMAX * DMODEL], g_ql[MMAX * DMODEL];
__device__ __align__(16) __nv_bfloat16 g_kh[MMAX * DMODEL], g_kl[MMAX * DMODEL];
__device__ __align__(16) __nv_bfloat16 g_vh[MMAX * DMODEL], g_vl[MMAX * DMODEL];

// ============================================================================
// helpers
// ============================================================================
__device__ __forceinline__ uint32_t smem_u32(const void* p) {
    uint32_t r;
    asm("{ .reg .u64 t; cvta.to.shared.u64 t, %1; cvt.u32.u64 %0, t; }" : "=r"(r) : "l"(p));
    return r;
}
__device__ __forceinline__ void split2(float v, __nv_bfloat16& h, __nv_bfloat16& l) {
    h = __float2bfloat16(v);
    l = __float2bfloat16(v - __bfloat162float(h));
}
__device__ __forceinline__ uint32_t pack2(__nv_bfloat16 a, __nv_bfloat16 b) {
    __nv_bfloat162 t = __halves2bfloat162(a, b);
    return *reinterpret_cast<uint32_t*>(&t);
}
__device__ __forceinline__ void cp16(uint32_t s, const void* g) {
    asm volatile("cp.async.cg.shared.global [%0], [%1], 16;" :: "r"(s), "l"(g));
}
__device__ __forceinline__ void cp_commit() {
    asm volatile("cp.async.commit_group;");
}
template <int N> __device__ __forceinline__ void cp_wait() {
    asm volatile("cp.async.wait_group %0;" :: "n"(N));
}
__device__ __forceinline__ void ldm_x4(uint32_t* r, uint32_t a) {
    asm volatile("ldmatrix.sync.aligned.m8n8.x4.shared.b16 {%0,%1,%2,%3}, [%4];"
                 : "=r"(r[0]), "=r"(r[1]), "=r"(r[2]), "=r"(r[3]) : "r"(a));
}
__device__ __forceinline__ void ldm_x4t(uint32_t* r, uint32_t a) {
    asm volatile("ldmatrix.sync.aligned.m8n8.x4.trans.shared.b16 {%0,%1,%2,%3}, [%4];"
                 : "=r"(r[0]), "=r"(r[1]), "=r"(r[2]), "=r"(r[3]) : "r"(a));
}
__device__ __forceinline__ void mma16816(float* d, const uint32_t* a, uint32_t b0, uint32_t b1) {
    asm volatile(
        "mma.sync.aligned.m16n8k16.row.col.f32.bf16.bf16.f32 "
        "{%0,%1,%2,%3}, {%4,%5,%6,%7}, {%8,%9}, {%0,%1,%2,%3};"
        : "+f"(d[0]), "+f"(d[1]), "+f"(d[2]), "+f"(d[3])
        : "r"(a[0]), "r"(a[1]), "r"(a[2]), "r"(a[3]), "r"(b0), "r"(b1));
}

// ============================================================================
// conversion: A[M,1024] fp32 -> hi/lo bf16 planes, row-major
// ============================================================================
__global__ __launch_bounds__(256) void conv_split_a(
    const float* __restrict__ A, __nv_bfloat16* __restrict__ dst, int M)
{
    int idx = blockIdx.x * 256 + threadIdx.x;
    if (idx >= M * 256) return;
    int row = idx >> 8, kg = idx & 255;
    float4 v = *(const float4*)(A + (size_t)row * DMODEL + kg * 4);
    __nv_bfloat16 h0, h1, h2, h3, l0, l1, l2, l3;
    split2(v.x, h0, l0); split2(v.y, h1, l1); split2(v.z, h2, l2); split2(v.w, h3, l3);
    size_t off = (size_t)row * DMODEL + kg * 4;
    size_t loPl = (size_t)M * DMODEL;
    *(uint2*)(dst + off)        = make_uint2(pack2(h0, h1), pack2(h2, h3));
    *(uint2*)(dst + loPl + off) = make_uint2(pack2(l0, l1), pack2(l2, l3));
}

__global__ __launch_bounds__(256) void conv_split_w(
    const float* __restrict__ W, __nv_bfloat16* __restrict__ dst)
{
    int idx = blockIdx.x * 256 + threadIdx.x;
    int kg = idx >> 10, n = idx & 1023;
    int k0 = kg * 4;
    float a0 = W[(size_t)(k0 + 0) * DMODEL + n];
    float a1 = W[(size_t)(k0 + 1) * DMODEL + n];
    float a2 = W[(size_t)(k0 + 2) * DMODEL + n];
    float a3 = W[(size_t)(k0 + 3) * DMODEL + n];
    __nv_bfloat16 h0, h1, h2, h3, l0, l1, l2, l3;
    split2(a0, h0, l0); split2(a1, h1, l1); split2(a2, h2, l2); split2(a3, h3, l3);
    size_t off = (size_t)n * DMODEL + k0;
    size_t loPl = (size_t)DMODEL * DMODEL;
    *(uint2*)(dst + off)        = make_uint2(pack2(h0, h1), pack2(h2, h3));
    *(uint2*)(dst + loPl + off) = make_uint2(pack2(l0, l1), pack2(l2, l3));
}

// ============================================================================
// mma.sync bf16x3 GEMM (verified round-3/4)
// mode 0: fp32 C row-major; mode 1: split hi/lo bf16 to (B,H,S,DK) planes
// ============================================================================
#define SROW   80
#define PLANE  (128 * SROW)
#define STAGE  (4 * PLANE)
#define GEMM_SMEM (2 * STAGE)

__global__ __launch_bounds__(256) void gemm_mma(
    const __nv_bfloat16* __restrict__ aP, const __nv_bfloat16* __restrict__ wP,
    const float* __restrict__ bias, float* __restrict__ C,
    __nv_bfloat16* __restrict__ outH, __nv_bfloat16* __restrict__ outL,
    int M, int mode, float scale)
{
    extern __shared__ unsigned char dyn[];
    const uint32_t sbase = smem_u32(dyn);

    const int tid = threadIdx.x, lane = tid & 31, wid = tid >> 5;
    const int mw = wid >> 2, nw = wid & 3;
    const int rowBase = blockIdx.y * 128, colBase = blockIdx.x * 128;

    const __nv_bfloat16* aHi = aP + (size_t)rowBase * DMODEL;
    const __nv_bfloat16* aLo = aHi + (size_t)M * DMODEL;
    const __nv_bfloat16* bHi = wP + (size_t)colBase * DMODEL;
    const __nv_bfloat16* bLo = bHi + (size_t)DMODEL * DMODEL;

    const int r0 = tid >> 2, c0 = (tid & 3) << 4;
    const int r1 = r0 + 64;

    auto load_stage = [&](int kt, int s) {
        const uint32_t sb = sbase + s * STAGE;
        const size_t g0 = (size_t)r0 * DMODEL + kt * 32;
        const size_t g1 = (size_t)r1 * DMODEL + kt * 32;
        const uint32_t s0 = r0 * SROW + c0, s1 = r1 * SROW + c0;
        cp16(sb + 0 * PLANE + s0, (const char*)(aHi + g0) + c0);
        cp16(sb + 0 * PLANE + s1, (const char*)(aHi + g1) + c0);
        cp16(sb + 1 * PLANE + s0, (const char*)(aLo + g0) + c0);
        cp16(sb + 1 * PLANE + s1, (const char*)(aLo + g1) + c0);
        cp16(sb + 2 * PLANE + s0, (const char*)(bHi + g0) + c0);
        cp16(sb + 2 * PLANE + s1, (const char*)(bHi + g1) + c0);
        cp16(sb + 3 * PLANE + s0, (const char*)(bLo + g0) + c0);
        cp16(sb + 3 * PLANE + s1, (const char*)(bLo + g1) + c0);
    };

    float acc[4][4][4] = {};
    const int lr = lane & 15, lc = lane >> 4;

    load_stage(0, 0);
    cp_commit();

    const int NIT = DMODEL / 32;
    for (int kt = 0; kt < NIT; kt++) {
        if (kt + 1 < NIT) load_stage(kt + 1, (kt + 1) & 1);
        cp_commit();
        cp_wait<1>();
        __syncthreads();

        const uint32_t sb = sbase + (kt & 1) * STAGE;
        #pragma unroll
        for (int kk = 0; kk < 2; kk++) {
            uint32_t ah[4][4], al[4][4], bh[2][4], bl[2][4];
            #pragma unroll
            for (int mi = 0; mi < 4; mi++) {
                uint32_t ra = sb + (mw * 64 + mi * 16 + lr) * SROW + kk * 32 + lc * 16;
                ldm_x4(ah[mi], ra);
                ldm_x4(al[mi], ra + PLANE);
            }
            #pragma unroll
            for (int ni = 0; ni < 2; ni++) {
                uint32_t rb = sb + 2 * PLANE + (nw * 32 + ni * 16 + lr) * SROW + kk * 32 + lc * 16;
                ldm_x4(bh[ni], rb);
                ldm_x4(bl[ni], rb + PLANE);
            }
            #pragma unroll
            for (int mi = 0; mi < 4; mi++) {
                #pragma unroll
                for (int n8 = 0; n8 < 4; n8++) {
                    const int ni = n8 >> 1, hf = n8 & 1;
                    mma16816(acc[mi][n8], ah[mi], bh[ni][hf], bh[ni][hf + 2]);
                    mma16816(acc[mi][n8], al[mi], bh[ni][hf], bh[ni][hf + 2]);
                    mma16816(acc[mi][n8], ah[mi], bl[ni][hf], bl[ni][hf + 2]);
                }
            }
        }
        __syncthreads();
    }

    const int wr = rowBase + mw * 64, wc = colBase + nw * 32;
    #pragma unroll
    for (int mi = 0; mi < 4; mi++) {
        #pragma unroll
        for (int n8 = 0; n8 < 4; n8++) {
            const int col = wc + n8 * 8 + (lane & 3) * 2;
            const float b0 = bias[col], b1 = bias[col + 1];
            #pragma unroll
            for (int h = 0; h < 2; h++) {
                const int row = wr + mi * 16 + (lane >> 2) + 8 * h;
                float ox = (acc[mi][n8][2 * h + 0] + b0) * scale;
                float oy = (acc[mi][n8][2 * h + 1] + b1) * scale;
                if (mode) {
                    int bb = row >> 11, ss = row & 2047;
                    int hh = col >> 6, dd = col & 63;
                    size_t e = ((size_t)(bb * NHEADS + hh) * S_LEN + ss) * DK + dd;
                    __nv_bfloat16 hx, lx, hy, ly;
                    split2(ox, hx, lx); split2(oy, hy, ly);
                    *(uint32_t*)(outH + e) = pack2(hx, hy);
                    *(uint32_t*)(outL + e) = pack2(lx, ly);
                } else {
                    float2 o; o.x = ox; o.y = oy;
                    *(float2*)&C[(size_t)row * DMODEL + col] = o;
                }
            }
        }
    }
}

// ============================================================================
// FA2 attention, mma.sync bf16x3. CTA: 128 q-rows, 4 warps x 32 q-rows.
// kv tile 64, double-buffered cp.async. Epilogue writes hi/lo bf16 planes
// in (B,S,H*Dk) row-major for the O-projection GEMM.
// ============================================================================
#define AT_SROW  144                  // 64 bf16 = 128B + 16 pad
#define AT_PLANE (64 * AT_SROW)       // 9216
#define AT_STAGE (4 * AT_PLANE)       // Kh Kl Vh Vl = 36864
#define ATT_SMEM (2 * AT_STAGE)       // 73728

__global__ __launch_bounds__(128) void attn_mma(
    const __nv_bfloat16* __restrict__ qhG, const __nv_bfloat16* __restrict__ qlG,
    const __nv_bfloat16* __restrict__ khG, const __nv_bfloat16* __restrict__ klG,
    const __nv_bfloat16* __restrict__ vhG, const __nv_bfloat16* __restrict__ vlG,
    __nv_bfloat16* __restrict__ outH, __nv_bfloat16* __restrict__ outL)
{
    extern __shared__ unsigned char dyn[];
    const uint32_t sb = smem_u32(dyn);
    const int tid = threadIdx.x, lane = tid & 31, wid = tid >> 5;   // 4 warps
    const int q0 = blockIdx.x * 128, h = blockIdx.y, b = blockIdx.z;
    const size_t hb = (size_t)(b * NHEADS + h) * S_LEN * DK;

    const char* qhB = (const char*)(qhG + hb);
    const char* qlB = (const char*)(qlG + hb);
    const char* khB = (const char*)(khG + hb);
    const char* klB = (const char*)(klG + hb);
    const char* vhB = (const char*)(vhG + hb);
    const char* vlB = (const char*)(vlG + hb);

    // ---- stage Q tile (hi/lo) through smem, extract fragments ----
    #pragma unroll
    for (int i = 0; i < 16; i++) {
        int cid = tid + 128 * i;               // 2048 chunks of 16B
        int pl = cid >> 10;                    // 0 hi, 1 lo
        int r  = (cid >> 3) & 127;
        int c  = (cid & 7) * 16;
        const char* g = (pl ? qlB : qhB) + (size_t)(q0 + r) * (DK * 2) + c;
        cp16(sb + pl * (128 * AT_SROW) + r * AT_SROW + c, g);
    }
    cp_commit(); cp_wait<0>(); __syncthreads();

    const int lr = lane & 15, lc = lane >> 4;
    uint32_t qfh[2][4][4], qfl[2][4][4];
    #pragma unroll
    for (int mi = 0; mi < 2; mi++) {
        #pragma unroll
        for (int ks = 0; ks < 4; ks++) {
            uint32_t a = sb + (wid * 32 + mi * 16 + lr) * AT_SROW + ks * 32 + lc * 16;
            ldm_x4(qfh[mi][ks], a);
            ldm_x4(qfl[mi][ks], a + 128 * AT_SROW);
        }
    }
    __syncthreads();

    float o[2][8][4] = {};
    float mS[2][2] = {{-1e30f, -1e30f}, {-1e30f, -1e30f}};
    float lS[2][2] = {};

    auto load_kv = [&](int t, int s) {
        const uint32_t st = sb + s * AT_STAGE;
        #pragma unroll
        for (int i = 0; i < 16; i++) {
            int cid = tid + 128 * i;           // 2048 chunks
            int pl = cid >> 9;                 // 0 kh, 1 kl, 2 vh, 3 vl
            int r  = (cid >> 3) & 63;
            int c  = (cid & 7) * 16;
            const char* g = (pl == 0) ? khB : (pl == 1) ? klB : (pl == 2) ? vhB : vlB;
            g += (size_t)(t * 64 + r) * (DK * 2) + c;
            cp16(st + pl * AT_PLANE + r * AT_SROW + c, g);
        }
    };

    load_kv(0, 0);
    cp_commit();

    const int NT = S_LEN / 64;
    for (int t = 0; t < NT; t++) {
        if (t + 1 < NT) load_kv(t + 1, (t + 1) & 1);
        cp_commit();
        cp_wait<1>();
        __syncthreads();
        const uint32_t st = sb + (t & 1) * AT_STAGE;

        // ---- S = Q K^T (bf16x3) ----
        float s[2][8][4] = {};
        #pragma unroll
        for (int g = 0; g < 4; g++) {
            #pragma unroll
            for (int ks = 0; ks < 4; ks++) {
                uint32_t kfh[4], kfl[4];
                uint32_t a = st + (g * 16 + lr) * AT_SROW + ks * 32 + lc * 16;
                ldm_x4(kfh, a);
                ldm_x4(kfl, a + AT_PLANE);
                #pragma unroll
                for (int mi = 0; mi < 2; mi++) {
                    #pragma unroll
                    for (int hf = 0; hf < 2; hf++) {
                        mma16816(s[mi][2 * g + hf], qfh[mi][ks], kfh[hf], kfh[hf + 2]);
                        mma16816(s[mi][2 * g + hf], qfl[mi][ks], kfh[hf], kfh[hf + 2]);
                        mma16816(s[mi][2 * g + hf], qfh[mi][ks], kfl[hf], kfl[hf + 2]);
                    }
                }
            }
        }

        // ---- online softmax + P fragments, per m-tile ----
        uint32_t ph[2][4][4], pq[2][4][4];
        #pragma unroll
        for (int mi = 0; mi < 2; mi++) {
            float mx0 = -1e30f, mx1 = -1e30f;
            #pragma unroll
            for (int j = 0; j < 8; j++) {
                mx0 = fmaxf(mx0, fmaxf(s[mi][j][0], s[mi][j][1]));
                mx1 = fmaxf(mx1, fmaxf(s[mi][j][2], s[mi][j][3]));
            }
            mx0 = fmaxf(mx0, __shfl_xor_sync(0xffffffffu, mx0, 1));
            mx0 = fmaxf(mx0, __shfl_xor_sync(0xffffffffu, mx0, 2));
            mx1 = fmaxf(mx1, __shfl_xor_sync(0xffffffffu, mx1, 1));
            mx1 = fmaxf(mx1, __shfl_xor_sync(0xffffffffu, mx1, 2));
            const float mn0 = fmaxf(mS[mi][0], mx0), mn1 = fmaxf(mS[mi][1], mx1);
            const float c0 = __expf(mS[mi][0] - mn0), c1 = __expf(mS[mi][1] - mn1);
            float ls0 = 0.f, ls1 = 0.f;
            #pragma unroll
            for (int j = 0; j < 8; j++) {
                s[mi][j][0] = __expf(s[mi][j][0] - mn0);
                s[mi][j][1] = __expf(s[mi][j][1] - mn0);
                s[mi][j][2] = __expf(s[mi][j][2] - mn1);
                s[mi][j][3] = __expf(s[mi][j][3] - mn1);
                ls0 += s[mi][j][0] + s[mi][j][1];
                ls1 += s[mi][j][2] + s[mi][j][3];
            }
            ls0 += __shfl_xor_sync(0xffffffffu, ls0, 1);
            ls0 += __shfl_xor_sync(0xffffffffu, ls0, 2);
            ls1 += __shfl_xor_sync(0xffffffffu, ls1, 1);
            ls1 += __shfl_xor_sync(0xffffffffu, ls1, 2);
            lS[mi][0] = lS[mi][0] * c0 + ls0;
            lS[mi][1] = lS[mi][1] * c1 + ls1;
            mS[mi][0] = mn0;  mS[mi][1] = mn1;
            #pragma unroll
            for (int j = 0; j < 8; j++) {
                o[mi][j][0] *= c0; o[mi][j][1] *= c0;
                o[mi][j][2] *= c1; o[mi][j][3] *= c1;
            }
            // P -> A fragments (hi/lo), verified mapping from round 4
            #pragma unroll
            for (int k = 0; k < 4; k++) {
                #pragma unroll
                for (int u = 0; u < 4; u++) {
                    const int jt = 2 * k + (u >> 1);
                    const int e  = (u & 1) * 2;
                    __nv_bfloat16 hx, lx, hy, ly;
                    split2(s[mi][jt][e + 0], hx, lx);
                    split2(s[mi][jt][e + 1], hy, ly);
                    ph[mi][k][u] = pack2(hx, hy);
                    pq[mi][k][u] = pack2(lx, ly);
                }
            }
        }

        // ---- O += P V (bf16x3), V via ldmatrix.trans ----
        #pragma unroll
        for (int d = 0; d < 4; d++) {
            #pragma unroll
            for (int k = 0; k < 4; k++) {
                uint32_t vfh[4], vfl[4];
                uint32_t a = st + 2 * AT_PLANE + (k * 16 + lr) * AT_SROW + d * 32 + lc * 16;
                ldm_x4t(vfh, a);
                ldm_x4t(vfl, a + AT_PLANE);
                #pragma unroll
                for (int mi = 0; mi < 2; mi++) {
                    mma16816(o[mi][2 * d + 0], ph[mi][k], vfh[0], vfh[1]);
                    mma16816(o[mi][2 * d + 0], pq[mi][k], vfh[0], vfh[1]);
                    mma16816(o[mi][2 * d + 0], ph[mi][k], vfl[0], vfl[1]);
                    mma16816(o[mi][2 * d + 1], ph[mi][k], vfh[2], vfh[3]);
                    mma16816(o[mi][2 * d + 1], pq[mi][k], vfh[2], vfh[3]);
                    mma16816(o[mi][2 * d + 1], ph[mi][k], vfl[2], vfl[3]);
                }
            }
        }
        __syncthreads();
    }

    // ---- epilogue: /l, split hi/lo bf16, write (B,S,H*Dk) planes ----
    const int cb = (lane & 3) * 2;
    #pragma unroll
    for (int mi = 0; mi < 2; mi++) {
        const float inv0 = 1.0f / lS[mi][0], inv1 = 1.0f / lS[mi][1];
        const int row0 = q0 + wid * 32 + mi * 16 + (lane >> 2);
        #pragma unroll
        for (int j = 0; j < 8; j++) {
            const int col = h * DK + j * 8 + cb;
            const size_t e0 = ((size_t)b * S_LEN + row0) * DMODEL + col;
            const size_t e1 = e0 + 8 * DMODEL;
            __nv_bfloat16 hx, lx, hy, ly;
            split2(o[mi][j][0] * inv0, hx, lx);
            split2(o[mi][j][1] * inv0, hy, ly);
            *(uint32_t*)(outH + e0) = pack2(hx, hy);
            *(uint32_t*)(outL + e0) = pack2(lx, ly);
            split2(o[mi][j][2] * inv1, hx, lx);
            split2(o[mi][j][3] * inv1, hy, ly);
            *(uint32_t*)(outH + e1) = pack2(hx, hy);
            *(uint32_t*)(outL + e1) = pack2(lx, ly);
        }
    }
}

// ============================================================================
extern "C" void kernel_launch(void* const* d_in, const int* in_sizes, int n_in,
                              void* d_out, int out_size)
{
    const float* Q  = (const float*)d_in[0];
    const float* K_ = (const float*)d_in[1];
    const float* V  = (const float*)d_in[2];
    const float* Wq = (const float*)d_in[3];
    const float* bq = (const float*)d_in[4];
    const float* Wk = (const float*)d_in[5];
    const float* bk = (const float*)d_in[6];
    const float* Wv = (const float*)d_in[7];
    const float* bv = (const float*)d_in[8];
    const float* Wo = (const float*)d_in[9];
    const float* bo = (const float*)d_in[10];

    int B = in_sizes[0] / (S_LEN * DMODEL);
    if (B > MAXB) B = MAXB;
    const int M = B * S_LEN;

    __nv_bfloat16 *aP, *wP, *qh, *ql, *kh, *kl, *vh, *vl;
    cudaGetSymbolAddress((void**)&aP, g_a16);
    cudaGetSymbolAddress((void**)&wP, g_w16);
    cudaGetSymbolAddress((void**)&qh, g_qh);
    cudaGetSymbolAddress((void**)&ql, g_ql);
    cudaGetSymbolAddress((void**)&kh, g_kh);
    cudaGetSymbolAddress((void**)&kl, g_kl);
    cudaGetSymbolAddress((void**)&vh, g_vh);
    cudaGetSymbolAddress((void**)&vl, g_vl);
    const size_t WSZ = 2ull * DMODEL * DMODEL;

    cudaFuncSetAttribute(gemm_mma, cudaFuncAttributeMaxDynamicSharedMemorySize, GEMM_SMEM);
    cudaFuncSetAttribute(attn_mma, cudaFuncAttributeMaxDynamicSharedMemorySize, ATT_SMEM);

    conv_split_w<<<1024, 256>>>(Wq, wP + 0 * WSZ);
    conv_split_w<<<1024, 256>>>(Wk, wP + 1 * WSZ);
    conv_split_w<<<1024, 256>>>(Wv, wP + 2 * WSZ);
    conv_split_w<<<1024, 256>>>(Wo, wP + 3 * WSZ);

    dim3 gg(DMODEL / 128, M / 128);

    conv_split_a<<<M, 256>>>(Q, aP, M);
    gemm_mma<<<gg, 256, GEMM_SMEM>>>(aP, wP + 0 * WSZ, bq, nullptr, qh, ql, M, 1, 0.125f);
    conv_split_a<<<M, 256>>>(K_, aP, M);
    gemm_mma<<<gg, 256, GEMM_SMEM>>>(aP, wP + 1 * WSZ, bk, nullptr, kh, kl, M, 1, 1.0f);
    conv_split_a<<<M, 256>>>(V, aP, M);
    gemm_mma<<<gg, 256, GEMM_SMEM>>>(aP, wP + 2 * WSZ, bv, nullptr, vh, vl, M, 1, 1.0f);

    // attention writes hi/lo bf16 planes directly into the O-projection A buffer
    attn_mma<<<dim3(S_LEN / 128, NHEADS, B), 128, ATT_SMEM>>>(
        qh, ql, kh, kl, vh, vl, aP, aP + (size_t)M * DMODEL);

    gemm_mma<<<gg, 256, GEMM_SMEM>>>(aP, wP + 3 * WSZ, bo, (float*)d_out, nullptr, nullptr, M, 0, 1.0f);
}

// round 6
// speedup vs baseline: 4.0930x; 1.6657x over previous
#include <cuda_runtime.h>
#include <cuda_fp16.h>
#include <math.h>
#include <stdint.h>

#define S_LEN  2048
#define DMODEL 1024
#define NHEADS 16
#define DK     64
#define MAXB   2
#define MMAX   (MAXB * S_LEN)      // 4096

// ---- scratch (device globals: allocation-free) ----
// single fp16 activation plane (GEMM A-side / attention output)
__device__ __align__(16) __half g_a16[MMAX * DMODEL];                    // 8 MB
// weights: hi/lo fp16 planes, transposed [N][K]
__device__ __align__(16) __half g_w16[4][2ull * DMODEL * DMODEL];        // 4 x 4 MB
// q hi/lo, k/v single, layout (B,H,S,DK)
__device__ __align__(16) __half g_qh[MMAX * DMODEL], g_ql[MMAX * DMODEL];
__device__ __align__(16) __half g_kh[MMAX * DMODEL];
__device__ __align__(16) __half g_vh[MMAX * DMODEL];

// ============================================================================
// helpers
// ============================================================================
__device__ __forceinline__ uint32_t smem_u32(const void* p) {
    uint32_t r;
    asm("{ .reg .u64 t; cvta.to.shared.u64 t, %1; cvt.u32.u64 %0, t; }" : "=r"(r) : "l"(p));
    return r;
}
__device__ __forceinline__ void split2h(float v, __half& h, __half& l) {
    h = __float2half_rn(v);
    l = __float2half_rn(v - __half2float(h));
}
__device__ __forceinline__ uint32_t pack2h(__half a, __half b) {
    __half2 t = __halves2half2(a, b);
    return *reinterpret_cast<uint32_t*>(&t);
}
__device__ __forceinline__ void cp16(uint32_t s, const void* g) {
    asm volatile("cp.async.cg.shared.global [%0], [%1], 16;" :: "r"(s), "l"(g));
}
__device__ __forceinline__ void cp_commit() {
    asm volatile("cp.async.commit_group;");
}
template <int N> __device__ __forceinline__ void cp_wait() {
    asm volatile("cp.async.wait_group %0;" :: "n"(N));
}
__device__ __forceinline__ void ldm_x4(uint32_t* r, uint32_t a) {
    asm volatile("ldmatrix.sync.aligned.m8n8.x4.shared.b16 {%0,%1,%2,%3}, [%4];"
                 : "=r"(r[0]), "=r"(r[1]), "=r"(r[2]), "=r"(r[3]) : "r"(a));
}
__device__ __forceinline__ void ldm_x4t(uint32_t* r, uint32_t a) {
    asm volatile("ldmatrix.sync.aligned.m8n8.x4.trans.shared.b16 {%0,%1,%2,%3}, [%4];"
                 : "=r"(r[0]), "=r"(r[1]), "=r"(r[2]), "=r"(r[3]) : "r"(a));
}
__device__ __forceinline__ void mma16816(float* d, const uint32_t* a, uint32_t b0, uint32_t b1) {
    asm volatile(
        "mma.sync.aligned.m16n8k16.row.col.f32.f16.f16.f32 "
        "{%0,%1,%2,%3}, {%4,%5,%6,%7}, {%8,%9}, {%0,%1,%2,%3};"
        : "+f"(d[0]), "+f"(d[1]), "+f"(d[2]), "+f"(d[3])
        : "r"(a[0]), "r"(a[1]), "r"(a[2]), "r"(a[3]), "r"(b0), "r"(b1));
}

// ============================================================================
// conversions
// ============================================================================
// A[M,1024] fp32 -> single fp16 plane, row-major
__global__ __launch_bounds__(256) void conv_single_a(
    const float* __restrict__ A, __half* __restrict__ dst, int M)
{
    int idx = blockIdx.x * 256 + threadIdx.x;
    if (idx >= M * 256) return;
    int row = idx >> 8, kg = idx & 255;
    float4 v = *(const float4*)(A + (size_t)row * DMODEL + kg * 4);
    size_t off = (size_t)row * DMODEL + kg * 4;
    *(uint2*)(dst + off) = make_uint2(
        pack2h(__float2half_rn(v.x), __float2half_rn(v.y)),
        pack2h(__float2half_rn(v.z), __float2half_rn(v.w)));
}

// W[1024,1024] fp32 (k-major rows) -> transposed hi/lo fp16 planes [N][K]
__global__ __launch_bounds__(256) void conv_split_w(
    const float* __restrict__ W, __half* __restrict__ dst)
{
    int idx = blockIdx.x * 256 + threadIdx.x;
    int kg = idx >> 10, n = idx & 1023;
    int k0 = kg * 4;
    float a0 = W[(size_t)(k0 + 0) * DMODEL + n];
    float a1 = W[(size_t)(k0 + 1) * DMODEL + n];
    float a2 = W[(size_t)(k0 + 2) * DMODEL + n];
    float a3 = W[(size_t)(k0 + 3) * DMODEL + n];
    __half h0, h1, h2, h3, l0, l1, l2, l3;
    split2h(a0, h0, l0); split2h(a1, h1, l1); split2h(a2, h2, l2); split2h(a3, h3, l3);
    size_t off = (size_t)n * DMODEL + k0;
    size_t loPl = (size_t)DMODEL * DMODEL;
    *(uint2*)(dst + off)        = make_uint2(pack2h(h0, h1), pack2h(h2, h3));
    *(uint2*)(dst + loPl + off) = make_uint2(pack2h(l0, l1), pack2h(l2, l3));
}

// ============================================================================
// fp16 2-pass GEMM: C = (A*W + bias) * scale ;  A single fp16, W hi/lo split
// mode 0: fp32 C row-major; mode 1: hi/lo fp16 (B,H,S,DK); mode 2: single fp16 (B,H,S,DK)
// ============================================================================
#define SROW   80            // 32 fp16 = 64B + 16 pad
#define PLANE  (128 * SROW)  // 10240
#define STAGE  (3 * PLANE)   // A, Wh, Wl
#define GEMM_SMEM (2 * STAGE)

__global__ __launch_bounds__(256) void gemm_mma(
    const __half* __restrict__ aP, const __half* __restrict__ wP,
    const float* __restrict__ bias, float* __restrict__ C,
    __half* __restrict__ outH, __half* __restrict__ outL,
    int M, int mode, float scale)
{
    extern __shared__ unsigned char dyn[];
    const uint32_t sbase = smem_u32(dyn);

    const int tid = threadIdx.x, lane = tid & 31, wid = tid >> 5;
    const int mw = wid >> 2, nw = wid & 3;
    const int rowBase = blockIdx.y * 128, colBase = blockIdx.x * 128;

    const __half* aB  = aP + (size_t)rowBase * DMODEL;
    const __half* bHi = wP + (size_t)colBase * DMODEL;
    const __half* bLo = bHi + (size_t)DMODEL * DMODEL;

    const int r0 = tid >> 2, c0 = (tid & 3) << 4;
    const int r1 = r0 + 64;

    auto load_stage = [&](int kt, int s) {
        const uint32_t sb = sbase + s * STAGE;
        const size_t g0 = (size_t)r0 * DMODEL + kt * 32;
        const size_t g1 = (size_t)r1 * DMODEL + kt * 32;
        const uint32_t s0 = r0 * SROW + c0, s1 = r1 * SROW + c0;
        cp16(sb + 0 * PLANE + s0, (const char*)(aB + g0) + c0);
        cp16(sb + 0 * PLANE + s1, (const char*)(aB + g1) + c0);
        cp16(sb + 1 * PLANE + s0, (const char*)(bHi + g0) + c0);
        cp16(sb + 1 * PLANE + s1, (const char*)(bHi + g1) + c0);
        cp16(sb + 2 * PLANE + s0, (const char*)(bLo + g0) + c0);
        cp16(sb + 2 * PLANE + s1, (const char*)(bLo + g1) + c0);
    };

    float acc[4][4][4] = {};
    const int lr = lane & 15, lc = lane >> 4;

    load_stage(0, 0);
    cp_commit();

    const int NIT = DMODEL / 32;
    for (int kt = 0; kt < NIT; kt++) {
        if (kt + 1 < NIT) load_stage(kt + 1, (kt + 1) & 1);
        cp_commit();
        cp_wait<1>();
        __syncthreads();

        const uint32_t sb = sbase + (kt & 1) * STAGE;
        #pragma unroll
        for (int kk = 0; kk < 2; kk++) {
            uint32_t ah[4][4], bh[2][4], bl[2][4];
            #pragma unroll
            for (int mi = 0; mi < 4; mi++) {
                uint32_t ra = sb + (mw * 64 + mi * 16 + lr) * SROW + kk * 32 + lc * 16;
                ldm_x4(ah[mi], ra);
            }
            #pragma unroll
            for (int ni = 0; ni < 2; ni++) {
                uint32_t rb = sb + 1 * PLANE + (nw * 32 + ni * 16 + lr) * SROW + kk * 32 + lc * 16;
                ldm_x4(bh[ni], rb);
                ldm_x4(bl[ni], rb + PLANE);
            }
            #pragma unroll
            for (int mi = 0; mi < 4; mi++) {
                #pragma unroll
                for (int n8 = 0; n8 < 4; n8++) {
                    const int ni = n8 >> 1, hf = n8 & 1;
                    mma16816(acc[mi][n8], ah[mi], bh[ni][hf], bh[ni][hf + 2]);
                    mma16816(acc[mi][n8], ah[mi], bl[ni][hf], bl[ni][hf + 2]);
                }
            }
        }
        __syncthreads();
    }

    const int wr = rowBase + mw * 64, wc = colBase + nw * 32;
    #pragma unroll
    for (int mi = 0; mi < 4; mi++) {
        #pragma unroll
        for (int n8 = 0; n8 < 4; n8++) {
            const int col = wc + n8 * 8 + (lane & 3) * 2;
            const float b0 = bias[col], b1 = bias[col + 1];
            #pragma unroll
            for (int h = 0; h < 2; h++) {
                const int row = wr + mi * 16 + (lane >> 2) + 8 * h;
                float ox = (acc[mi][n8][2 * h + 0] + b0) * scale;
                float oy = (acc[mi][n8][2 * h + 1] + b1) * scale;
                if (mode == 0) {
                    float2 o; o.x = ox; o.y = oy;
                    *(float2*)&C[(size_t)row * DMODEL + col] = o;
                } else {
                    int bb = row >> 11, ss = row & 2047;
                    int hh = col >> 6, dd = col & 63;
                    size_t e = ((size_t)(bb * NHEADS + hh) * S_LEN + ss) * DK + dd;
                    if (mode == 1) {
                        __half hx, lx, hy, ly;
                        split2h(ox, hx, lx); split2h(oy, hy, ly);
                        *(uint32_t*)(outH + e) = pack2h(hx, hy);
                        *(uint32_t*)(outL + e) = pack2h(lx, ly);
                    } else {
                        *(uint32_t*)(outH + e) = pack2h(__float2half_rn(ox), __float2half_rn(oy));
                    }
                }
            }
        }
    }
}

// ============================================================================
// FA2 attention, fp16 2-pass. CTA: 128 q-rows, 4 warps x 32 q-rows.
// Q hi/lo (regs), K single, V single; P split hi/lo in regs.
// Epilogue writes single fp16 (B,S,H*Dk) plane for the O-projection.
// ============================================================================
#define AT_SROW  144                  // 64 fp16 = 128B + 16 pad
#define AT_PLANE (64 * AT_SROW)       // 9216
#define AT_STAGE (2 * AT_PLANE)       // K, V = 18432
#define ATT_SMEM (2 * AT_STAGE)       // 36864 (Q staging reuses the same 36864)

__global__ __launch_bounds__(128) void attn_mma(
    const __half* __restrict__ qhG, const __half* __restrict__ qlG,
    const __half* __restrict__ khG, const __half* __restrict__ vhG,
    __half* __restrict__ outA)
{
    extern __shared__ unsigned char dyn[];
    const uint32_t sb = smem_u32(dyn);
    const int tid = threadIdx.x, lane = tid & 31, wid = tid >> 5;   // 4 warps
    const int q0 = blockIdx.x * 128, h = blockIdx.y, b = blockIdx.z;
    const size_t hb = (size_t)(b * NHEADS + h) * S_LEN * DK;

    const char* qhB = (const char*)(qhG + hb);
    const char* qlB = (const char*)(qlG + hb);
    const char* khB = (const char*)(khG + hb);
    const char* vhB = (const char*)(vhG + hb);

    // ---- stage Q tile (hi/lo) through smem, extract fragments ----
    #pragma unroll
    for (int i = 0; i < 16; i++) {
        int cid = tid + 128 * i;               // 2048 chunks of 16B
        int pl = cid >> 10;                    // 0 hi, 1 lo
        int r  = (cid >> 3) & 127;
        int c  = (cid & 7) * 16;
        const char* g = (pl ? qlB : qhB) + (size_t)(q0 + r) * (DK * 2) + c;
        cp16(sb + pl * (128 * AT_SROW) + r * AT_SROW + c, g);
    }
    cp_commit(); cp_wait<0>(); __syncthreads();

    const int lr = lane & 15, lc = lane >> 4;
    uint32_t qfh[2][4][4], qfl[2][4][4];
    #pragma unroll
    for (int mi = 0; mi < 2; mi++) {
        #pragma unroll
        for (int ks = 0; ks < 4; ks++) {
            uint32_t a = sb + (wid * 32 + mi * 16 + lr) * AT_SROW + ks * 32 + lc * 16;
            ldm_x4(qfh[mi][ks], a);
            ldm_x4(qfl[mi][ks], a + 128 * AT_SROW);
        }
    }
    __syncthreads();

    float o[2][8][4] = {};
    float mS[2][2] = {{-1e30f, -1e30f}, {-1e30f, -1e30f}};
    float lS[2][2] = {};

    auto load_kv = [&](int t, int s) {
        const uint32_t st = sb + s * AT_STAGE;
        #pragma unroll
        for (int i = 0; i < 8; i++) {
            int cid = tid + 128 * i;           // 1024 chunks
            int pl = cid >> 9;                 // 0 K, 1 V
            int r  = (cid >> 3) & 63;
            int c  = (cid & 7) * 16;
            const char* g = (pl == 0) ? khB : vhB;
            g += (size_t)(t * 64 + r) * (DK * 2) + c;
            cp16(st + pl * AT_PLANE + r * AT_SROW + c, g);
        }
    };

    load_kv(0, 0);
    cp_commit();

    const int NT = S_LEN / 64;
    for (int t = 0; t < NT; t++) {
        if (t + 1 < NT) load_kv(t + 1, (t + 1) & 1);
        cp_commit();
        cp_wait<1>();
        __syncthreads();
        const uint32_t st = sb + (t & 1) * AT_STAGE;

        // ---- S = Q K^T (Q hi/lo, K single) ----
        float s[2][8][4] = {};
        #pragma unroll
        for (int g = 0; g < 4; g++) {
            #pragma unroll
            for (int ks = 0; ks < 4; ks++) {
                uint32_t kf[4];
                uint32_t a = st + (g * 16 + lr) * AT_SROW + ks * 32 + lc * 16;
                ldm_x4(kf, a);
                #pragma unroll
                for (int mi = 0; mi < 2; mi++) {
                    #pragma unroll
                    for (int hf = 0; hf < 2; hf++) {
                        mma16816(s[mi][2 * g + hf], qfh[mi][ks], kf[hf], kf[hf + 2]);
                        mma16816(s[mi][2 * g + hf], qfl[mi][ks], kf[hf], kf[hf + 2]);
                    }
                }
            }
        }

        // ---- online softmax + P fragments, per m-tile ----
        uint32_t ph[2][4][4], pq[2][4][4];
        #pragma unroll
        for (int mi = 0; mi < 2; mi++) {
            float mx0 = -1e30f, mx1 = -1e30f;
            #pragma unroll
            for (int j = 0; j < 8; j++) {
                mx0 = fmaxf(mx0, fmaxf(s[mi][j][0], s[mi][j][1]));
                mx1 = fmaxf(mx1, fmaxf(s[mi][j][2], s[mi][j][3]));
            }
            mx0 = fmaxf(mx0, __shfl_xor_sync(0xffffffffu, mx0, 1));
            mx0 = fmaxf(mx0, __shfl_xor_sync(0xffffffffu, mx0, 2));
            mx1 = fmaxf(mx1, __shfl_xor_sync(0xffffffffu, mx1, 1));
            mx1 = fmaxf(mx1, __shfl_xor_sync(0xffffffffu, mx1, 2));
            const float mn0 = fmaxf(mS[mi][0], mx0), mn1 = fmaxf(mS[mi][1], mx1);
            const float c0 = __expf(mS[mi][0] - mn0), c1 = __expf(mS[mi][1] - mn1);
            float ls0 = 0.f, ls1 = 0.f;
            #pragma unroll
            for (int j = 0; j < 8; j++) {
                s[mi][j][0] = __expf(s[mi][j][0] - mn0);
                s[mi][j][1] = __expf(s[mi][j][1] - mn0);
                s[mi][j][2] = __expf(s[mi][j][2] - mn1);
                s[mi][j][3] = __expf(s[mi][j][3] - mn1);
                ls0 += s[mi][j][0] + s[mi][j][1];
                ls1 += s[mi][j][2] + s[mi][j][3];
            }
            ls0 += __shfl_xor_sync(0xffffffffu, ls0, 1);
            ls0 += __shfl_xor_sync(0xffffffffu, ls0, 2);
            ls1 += __shfl_xor_sync(0xffffffffu, ls1, 1);
            ls1 += __shfl_xor_sync(0xffffffffu, ls1, 2);
            lS[mi][0] = lS[mi][0] * c0 + ls0;
            lS[mi][1] = lS[mi][1] * c1 + ls1;
            mS[mi][0] = mn0;  mS[mi][1] = mn1;
            #pragma unroll
            for (int j = 0; j < 8; j++) {
                o[mi][j][0] *= c0; o[mi][j][1] *= c0;
                o[mi][j][2] *= c1; o[mi][j][3] *= c1;
            }
            // P -> A fragments (hi/lo), verified round-4 mapping
            #pragma unroll
            for (int k = 0; k < 4; k++) {
                #pragma unroll
                for (int u = 0; u < 4; u++) {
                    const int jt = 2 * k + (u >> 1);
                    const int e  = (u & 1) * 2;
                    __half hx, lx, hy, ly;
                    split2h(s[mi][jt][e + 0], hx, lx);
                    split2h(s[mi][jt][e + 1], hy, ly);
                    ph[mi][k][u] = pack2h(hx, hy);
                    pq[mi][k][u] = pack2h(lx, ly);
                }
            }
        }

        // ---- O += P V (P hi/lo, V single), V via ldmatrix.trans ----
        #pragma unroll
        for (int d = 0; d < 4; d++) {
            #pragma unroll
            for (int k = 0; k < 4; k++) {
                uint32_t vf[4];
                uint32_t a = st + AT_PLANE + (k * 16 + lr) * AT_SROW + d * 32 + lc * 16;
                ldm_x4t(vf, a);
                #pragma unroll
                for (int mi = 0; mi < 2; mi++) {
                    mma16816(o[mi][2 * d + 0], ph[mi][k], vf[0], vf[1]);
                    mma16816(o[mi][2 * d + 0], pq[mi][k], vf[0], vf[1]);
                    mma16816(o[mi][2 * d + 1], ph[mi][k], vf[2], vf[3]);
                    mma16816(o[mi][2 * d + 1], pq[mi][k], vf[2], vf[3]);
                }
            }
        }
        __syncthreads();
    }

    // ---- epilogue: /l, write single fp16 (B,S,H*Dk) plane ----
    const int cb = (lane & 3) * 2;
    #pragma unroll
    for (int mi = 0; mi < 2; mi++) {
        const float inv0 = 1.0f / lS[mi][0], inv1 = 1.0f / lS[mi][1];
        const int row0 = q0 + wid * 32 + mi * 16 + (lane >> 2);
        #pragma unroll
        for (int j = 0; j < 8; j++) {
            const int col = h * DK + j * 8 + cb;
            const size_t e0 = ((size_t)b * S_LEN + row0) * DMODEL + col;
            const size_t e1 = e0 + 8 * DMODEL;
            *(uint32_t*)(outA + e0) = pack2h(__float2half_rn(o[mi][j][0] * inv0),
                                             __float2half_rn(o[mi][j][1] * inv0));
            *(uint32_t*)(outA + e1) = pack2h(__float2half_rn(o[mi][j][2] * inv1),
                                             __float2half_rn(o[mi][j][3] * inv1));
        }
    }
}

// ============================================================================
extern "C" void kernel_launch(void* const* d_in, const int* in_sizes, int n_in,
                              void* d_out, int out_size)
{
    const float* Q  = (const float*)d_in[0];
    const float* K_ = (const float*)d_in[1];
    const float* V  = (const float*)d_in[2];
    const float* Wq = (const float*)d_in[3];
    const float* bq = (const float*)d_in[4];
    const float* Wk = (const float*)d_in[5];
    const float* bk = (const float*)d_in[6];
    const float* Wv = (const float*)d_in[7];
    const float* bv = (const float*)d_in[8];
    const float* Wo = (const float*)d_in[9];
    const float* bo = (const float*)d_in[10];

    int B = in_sizes[0] / (S_LEN * DMODEL);
    if (B > MAXB) B = MAXB;
    const int M = B * S_LEN;

    __half *aP, *wP, *qh, *ql, *kh, *vh;
    cudaGetSymbolAddress((void**)&aP, g_a16);
    cudaGetSymbolAddress((void**)&wP, g_w16);
    cudaGetSymbolAddress((void**)&qh, g_qh);
    cudaGetSymbolAddress((void**)&ql, g_ql);
    cudaGetSymbolAddress((void**)&kh, g_kh);
    cudaGetSymbolAddress((void**)&vh, g_vh);
    const size_t WSZ = 2ull * DMODEL * DMODEL;

    cudaFuncSetAttribute(gemm_mma, cudaFuncAttributeMaxDynamicSharedMemorySize, GEMM_SMEM);
    cudaFuncSetAttribute(attn_mma, cudaFuncAttributeMaxDynamicSharedMemorySize, ATT_SMEM);

    conv_split_w<<<1024, 256>>>(Wq, wP + 0 * WSZ);
    conv_split_w<<<1024, 256>>>(Wk, wP + 1 * WSZ);
    conv_split_w<<<1024, 256>>>(Wv, wP + 2 * WSZ);
    conv_split_w<<<1024, 256>>>(Wo, wP + 3 * WSZ);

    dim3 gg(DMODEL / 128, M / 128);

    conv_single_a<<<M, 256>>>(Q, aP, M);
    gemm_mma<<<gg, 256, GEMM_SMEM>>>(aP, wP + 0 * WSZ, bq, nullptr, qh, ql, M, 1, 0.125f);
    conv_single_a<<<M, 256>>>(K_, aP, M);
    gemm_mma<<<gg, 256, GEMM_SMEM>>>(aP, wP + 1 * WSZ, bk, nullptr, kh, nullptr, M, 2, 1.0f);
    conv_single_a<<<M, 256>>>(V, aP, M);
    gemm_mma<<<gg, 256, GEMM_SMEM>>>(aP, wP + 2 * WSZ, bv, nullptr, vh, nullptr, M, 2, 1.0f);

    // attention writes single fp16 plane directly into the O-projection A buffer
    attn_mma<<<dim3(S_LEN / 128, NHEADS, B), 128, ATT_SMEM>>>(qh, ql, kh, vh, aP);

    gemm_mma<<<gg, 256, GEMM_SMEM>>>(aP, wP + 3 * WSZ, bo, (float*)d_out, nullptr, nullptr, M, 0, 1.0f);
}

// round 7
// speedup vs baseline: 5.2833x; 1.2908x over previous
#include <cuda_runtime.h>
#include <cuda_fp16.h>
#include <math.h>
#include <stdint.h>

#define S_LEN  2048
#define DMODEL 1024
#define NHEADS 16
#define DK     64
#define MAXB   2
#define MMAX   (MAXB * S_LEN)      // 4096

// ---- scratch (device globals: allocation-free) ----
__device__ __align__(16) __half g_a16[MMAX * DMODEL];              // attn-out fp16 plane
__device__ __align__(16) __half g_w16[4][DMODEL * DMODEL];         // weights single fp16 [N][K]
__device__ __align__(16) __half g_qh[MMAX * DMODEL], g_ql[MMAX * DMODEL];
__device__ __align__(16) __half g_kh[MMAX * DMODEL];
__device__ __align__(16) __half g_vh[MMAX * DMODEL];

// ============================================================================
// helpers
// ============================================================================
__device__ __forceinline__ uint32_t smem_u32(const void* p) {
    uint32_t r;
    asm("{ .reg .u64 t; cvta.to.shared.u64 t, %1; cvt.u32.u64 %0, t; }" : "=r"(r) : "l"(p));
    return r;
}
__device__ __forceinline__ void split2h(float v, __half& h, __half& l) {
    h = __float2half_rn(v);
    l = __float2half_rn(v - __half2float(h));
}
__device__ __forceinline__ uint32_t pack2h(__half a, __half b) {
    __half2 t = __halves2half2(a, b);
    return *reinterpret_cast<uint32_t*>(&t);
}
__device__ __forceinline__ uint32_t packf2(float a, float b) {
    __half2 t = __floats2half2_rn(a, b);
    return *reinterpret_cast<uint32_t*>(&t);
}
__device__ __forceinline__ void cp16(uint32_t s, const void* g) {
    asm volatile("cp.async.cg.shared.global [%0], [%1], 16;" :: "r"(s), "l"(g));
}
__device__ __forceinline__ void cp_commit() {
    asm volatile("cp.async.commit_group;");
}
template <int N> __device__ __forceinline__ void cp_wait() {
    asm volatile("cp.async.wait_group %0;" :: "n"(N));
}
__device__ __forceinline__ void ldm_x4(uint32_t* r, uint32_t a) {
    asm volatile("ldmatrix.sync.aligned.m8n8.x4.shared.b16 {%0,%1,%2,%3}, [%4];"
                 : "=r"(r[0]), "=r"(r[1]), "=r"(r[2]), "=r"(r[3]) : "r"(a));
}
__device__ __forceinline__ void ldm_x4t(uint32_t* r, uint32_t a) {
    asm volatile("ldmatrix.sync.aligned.m8n8.x4.trans.shared.b16 {%0,%1,%2,%3}, [%4];"
                 : "=r"(r[0]), "=r"(r[1]), "=r"(r[2]), "=r"(r[3]) : "r"(a));
}
__device__ __forceinline__ void mma16816(float* d, const uint32_t* a, uint32_t b0, uint32_t b1) {
    asm volatile(
        "mma.sync.aligned.m16n8k16.row.col.f32.f16.f16.f32 "
        "{%0,%1,%2,%3}, {%4,%5,%6,%7}, {%8,%9}, {%0,%1,%2,%3};"
        : "+f"(d[0]), "+f"(d[1]), "+f"(d[2]), "+f"(d[3])
        : "r"(a[0]), "r"(a[1]), "r"(a[2]), "r"(a[3]), "r"(b0), "r"(b1));
}

// ============================================================================
// W[1024,1024] fp32 (k-major rows) -> transposed single fp16 plane [N][K]
// ============================================================================
__global__ __launch_bounds__(256) void conv_single_w(
    const float* __restrict__ W, __half* __restrict__ dst)
{
    int idx = blockIdx.x * 256 + threadIdx.x;
    int kg = idx >> 10, n = idx & 1023;
    int k0 = kg * 4;
    float a0 = W[(size_t)(k0 + 0) * DMODEL + n];
    float a1 = W[(size_t)(k0 + 1) * DMODEL + n];
    float a2 = W[(size_t)(k0 + 2) * DMODEL + n];
    float a3 = W[(size_t)(k0 + 3) * DMODEL + n];
    *(uint2*)(dst + (size_t)n * DMODEL + k0) = make_uint2(packf2(a0, a1), packf2(a2, a3));
}

// ============================================================================
// fp16 1-pass GEMM: C = (A*W + bias) * scale ; W single plane [N][K]
// aFp32=1: A is fp32 (converted on the fly via LDG->cvt->STS pipeline)
// mode 0: fp32 C row-major; mode 1: hi/lo fp16 (B,H,S,DK); mode 2: single fp16 (B,H,S,DK)
// ============================================================================
#define SROW   80            // 32 fp16 = 64B + 16 pad
#define PLANE  (128 * SROW)  // 10240
#define STAGE  (2 * PLANE)   // A, W
#define GEMM_SMEM (2 * STAGE)   // 40960

__global__ __launch_bounds__(256) void gemm_mma(
    const void* __restrict__ aIn, const __half* __restrict__ wP,
    const float* __restrict__ bias, float* __restrict__ C,
    __half* __restrict__ outH, __half* __restrict__ outL,
    int M, int aFp32, int mode, float scale)
{
    extern __shared__ unsigned char dyn[];
    const uint32_t sbase = smem_u32(dyn);

    const int tid = threadIdx.x, lane = tid & 31, wid = tid >> 5;
    const int mw = wid >> 2, nw = wid & 3;
    const int rowBase = blockIdx.y * 128, colBase = blockIdx.x * 128;

    const __half* bW = wP + (size_t)colBase * DMODEL;

    const int r0 = tid >> 2, c0 = (tid & 3) << 4;   // chunk mapping (16B units)
    const int r1 = r0 + 64;

    // --- W loader (cp.async) ---
    auto load_w = [&](int kt, int s) {
        const uint32_t sb = sbase + s * STAGE + PLANE;
        const size_t g0 = (size_t)r0 * DMODEL + kt * 32;
        const size_t g1 = (size_t)r1 * DMODEL + kt * 32;
        cp16(sb + r0 * SROW + c0, (const char*)(bW + g0) + c0);
        cp16(sb + r1 * SROW + c0, (const char*)(bW + g1) + c0);
    };
    // --- A loaders ---
    const __half* aH = (const __half*)aIn + (size_t)rowBase * DMODEL;   // fp16 path
    auto load_a16 = [&](int kt, int s) {
        const uint32_t sb = sbase + s * STAGE;
        const size_t g0 = (size_t)r0 * DMODEL + kt * 32;
        const size_t g1 = (size_t)r1 * DMODEL + kt * 32;
        cp16(sb + r0 * SROW + c0, (const char*)(aH + g0) + c0);
        cp16(sb + r1 * SROW + c0, (const char*)(aH + g1) + c0);
    };
    // fp32 path: LDG prefetch -> regs -> cvt -> STS
    const float* aF = (const float*)aIn;
    const int fc = (tid & 3) * 8;                    // 8 floats per row chunk
    float4 pf[4];
    auto ldg_a32 = [&](int kt) {
        const float* p0 = aF + (size_t)(rowBase + r0) * DMODEL + kt * 32 + fc;
        const float* p1 = aF + (size_t)(rowBase + r1) * DMODEL + kt * 32 + fc;
        pf[0] = *(const float4*)p0;  pf[1] = *(const float4*)(p0 + 4);
        pf[2] = *(const float4*)p1;  pf[3] = *(const float4*)(p1 + 4);
    };
    auto sts_a32 = [&](int s) {
        uint4 v0, v1;
        v0.x = packf2(pf[0].x, pf[0].y); v0.y = packf2(pf[0].z, pf[0].w);
        v0.z = packf2(pf[1].x, pf[1].y); v0.w = packf2(pf[1].z, pf[1].w);
        v1.x = packf2(pf[2].x, pf[2].y); v1.y = packf2(pf[2].z, pf[2].w);
        v1.z = packf2(pf[3].x, pf[3].y); v1.w = packf2(pf[3].z, pf[3].w);
        *(uint4*)(dyn + s * STAGE + r0 * SROW + c0) = v0;
        *(uint4*)(dyn + s * STAGE + r1 * SROW + c0) = v1;
    };

    float acc[4][4][4] = {};
    const int lr = lane & 15, lc = lane >> 4;

    // prologue
    if (aFp32) {
        ldg_a32(0); sts_a32(0); ldg_a32(1);
    } else {
        load_a16(0, 0);
    }
    load_w(0, 0);
    cp_commit();

    const int NIT = DMODEL / 32;
    for (int kt = 0; kt < NIT; kt++) {
        const int s = kt & 1;
        if (kt + 1 < NIT) {
            load_w(kt + 1, s ^ 1);
            if (!aFp32) load_a16(kt + 1, s ^ 1);
        }
        cp_commit();
        cp_wait<1>();
        __syncthreads();

        const uint32_t sb = sbase + s * STAGE;
        #pragma unroll
        for (int kk = 0; kk < 2; kk++) {
            uint32_t ah[4][4], bh[2][4];
            #pragma unroll
            for (int mi = 0; mi < 4; mi++) {
                uint32_t ra = sb + (mw * 64 + mi * 16 + lr) * SROW + kk * 32 + lc * 16;
                ldm_x4(ah[mi], ra);
            }
            #pragma unroll
            for (int ni = 0; ni < 2; ni++) {
                uint32_t rb = sb + PLANE + (nw * 32 + ni * 16 + lr) * SROW + kk * 32 + lc * 16;
                ldm_x4(bh[ni], rb);
            }
            #pragma unroll
            for (int mi = 0; mi < 4; mi++) {
                #pragma unroll
                for (int n8 = 0; n8 < 4; n8++) {
                    const int ni = n8 >> 1, hf = n8 & 1;
                    mma16816(acc[mi][n8], ah[mi], bh[ni][hf], bh[ni][hf + 2]);
                }
            }
        }
        if (aFp32 && kt + 1 < NIT) {
            sts_a32(s ^ 1);                 // A[kt+1] regs -> smem
            if (kt + 2 < NIT) ldg_a32(kt + 2);
        }
        __syncthreads();
    }

    const int wr = rowBase + mw * 64, wc = colBase + nw * 32;
    #pragma unroll
    for (int mi = 0; mi < 4; mi++) {
        #pragma unroll
        for (int n8 = 0; n8 < 4; n8++) {
            const int col = wc + n8 * 8 + (lane & 3) * 2;
            const float b0 = bias[col], b1 = bias[col + 1];
            #pragma unroll
            for (int h = 0; h < 2; h++) {
                const int row = wr + mi * 16 + (lane >> 2) + 8 * h;
                float ox = (acc[mi][n8][2 * h + 0] + b0) * scale;
                float oy = (acc[mi][n8][2 * h + 1] + b1) * scale;
                if (mode == 0) {
                    float2 o; o.x = ox; o.y = oy;
                    *(float2*)&C[(size_t)row * DMODEL + col] = o;
                } else {
                    int bb = row >> 11, ss = row & 2047;
                    int hh = col >> 6, dd = col & 63;
                    size_t e = ((size_t)(bb * NHEADS + hh) * S_LEN + ss) * DK + dd;
                    if (mode == 1) {
                        __half hx, lx, hy, ly;
                        split2h(ox, hx, lx); split2h(oy, hy, ly);
                        *(uint32_t*)(outH + e) = pack2h(hx, hy);
                        *(uint32_t*)(outL + e) = pack2h(lx, ly);
                    } else {
                        *(uint32_t*)(outH + e) = packf2(ox, oy);
                    }
                }
            }
        }
    }
}

// ============================================================================
// FA2 attention (verified round-6): fp16, Q hi/lo, K/V single, P hi/lo.
// CTA: 128 q-rows, 4 warps x 32 q-rows. Writes single fp16 plane for O-proj.
// ============================================================================
#define AT_SROW  144
#define AT_PLANE (64 * AT_SROW)
#define AT_STAGE (2 * AT_PLANE)
#define ATT_SMEM (2 * AT_STAGE)

__global__ __launch_bounds__(128) void attn_mma(
    const __half* __restrict__ qhG, const __half* __restrict__ qlG,
    const __half* __restrict__ khG, const __half* __restrict__ vhG,
    __half* __restrict__ outA)
{
    extern __shared__ unsigned char dyn[];
    const uint32_t sb = smem_u32(dyn);
    const int tid = threadIdx.x, lane = tid & 31, wid = tid >> 5;
    const int q0 = blockIdx.x * 128, h = blockIdx.y, b = blockIdx.z;
    const size_t hb = (size_t)(b * NHEADS + h) * S_LEN * DK;

    const char* qhB = (const char*)(qhG + hb);
    const char* qlB = (const char*)(qlG + hb);
    const char* khB = (const char*)(khG + hb);
    const char* vhB = (const char*)(vhG + hb);

    #pragma unroll
    for (int i = 0; i < 16; i++) {
        int cid = tid + 128 * i;
        int pl = cid >> 10;
        int r  = (cid >> 3) & 127;
        int c  = (cid & 7) * 16;
        const char* g = (pl ? qlB : qhB) + (size_t)(q0 + r) * (DK * 2) + c;
        cp16(sb + pl * (128 * AT_SROW) + r * AT_SROW + c, g);
    }
    cp_commit(); cp_wait<0>(); __syncthreads();

    const int lr = lane & 15, lc = lane >> 4;
    uint32_t qfh[2][4][4], qfl[2][4][4];
    #pragma unroll
    for (int mi = 0; mi < 2; mi++) {
        #pragma unroll
        for (int ks = 0; ks < 4; ks++) {
            uint32_t a = sb + (wid * 32 + mi * 16 + lr) * AT_SROW + ks * 32 + lc * 16;
            ldm_x4(qfh[mi][ks], a);
            ldm_x4(qfl[mi][ks], a + 128 * AT_SROW);
        }
    }
    __syncthreads();

    float o[2][8][4] = {};
    float mS[2][2] = {{-1e30f, -1e30f}, {-1e30f, -1e30f}};
    float lS[2][2] = {};

    auto load_kv = [&](int t, int s) {
        const uint32_t st = sb + s * AT_STAGE;
        #pragma unroll
        for (int i = 0; i < 8; i++) {
            int cid = tid + 128 * i;
            int pl = cid >> 9;
            int r  = (cid >> 3) & 63;
            int c  = (cid & 7) * 16;
            const char* g = (pl == 0) ? khB : vhB;
            g += (size_t)(t * 64 + r) * (DK * 2) + c;
            cp16(st + pl * AT_PLANE + r * AT_SROW + c, g);
        }
    };

    load_kv(0, 0);
    cp_commit();

    const int NT = S_LEN / 64;
    for (int t = 0; t < NT; t++) {
        if (t + 1 < NT) load_kv(t + 1, (t + 1) & 1);
        cp_commit();
        cp_wait<1>();
        __syncthreads();
        const uint32_t st = sb + (t & 1) * AT_STAGE;

        float s[2][8][4] = {};
        #pragma unroll
        for (int g = 0; g < 4; g++) {
            #pragma unroll
            for (int ks = 0; ks < 4; ks++) {
                uint32_t kf[4];
                uint32_t a = st + (g * 16 + lr) * AT_SROW + ks * 32 + lc * 16;
                ldm_x4(kf, a);
                #pragma unroll
                for (int mi = 0; mi < 2; mi++) {
                    #pragma unroll
                    for (int hf = 0; hf < 2; hf++) {
                        mma16816(s[mi][2 * g + hf], qfh[mi][ks], kf[hf], kf[hf + 2]);
                        mma16816(s[mi][2 * g + hf], qfl[mi][ks], kf[hf], kf[hf + 2]);
                    }
                }
            }
        }

        uint32_t ph[2][4][4], pq[2][4][4];
        #pragma unroll
        for (int mi = 0; mi < 2; mi++) {
            float mx0 = -1e30f, mx1 = -1e30f;
            #pragma unroll
            for (int j = 0; j < 8; j++) {
                mx0 = fmaxf(mx0, fmaxf(s[mi][j][0], s[mi][j][1]));
                mx1 = fmaxf(mx1, fmaxf(s[mi][j][2], s[mi][j][3]));
            }
            mx0 = fmaxf(mx0, __shfl_xor_sync(0xffffffffu, mx0, 1));
            mx0 = fmaxf(mx0, __shfl_xor_sync(0xffffffffu, mx0, 2));
            mx1 = fmaxf(mx1, __shfl_xor_sync(0xffffffffu, mx1, 1));
            mx1 = fmaxf(mx1, __shfl_xor_sync(0xffffffffu, mx1, 2));
            const float mn0 = fmaxf(mS[mi][0], mx0), mn1 = fmaxf(mS[mi][1], mx1);
            const float c0 = __expf(mS[mi][0] - mn0), c1 = __expf(mS[mi][1] - mn1);
            float ls0 = 0.f, ls1 = 0.f;
            #pragma unroll
            for (int j = 0; j < 8; j++) {
                s[mi][j][0] = __expf(s[mi][j][0] - mn0);
                s[mi][j][1] = __expf(s[mi][j][1] - mn0);
                s[mi][j][2] = __expf(s[mi][j][2] - mn1);
                s[mi][j][3] = __expf(s[mi][j][3] - mn1);
                ls0 += s[mi][j][0] + s[mi][j][1];
                ls1 += s[mi][j][2] + s[mi][j][3];
            }
            ls0 += __shfl_xor_sync(0xffffffffu, ls0, 1);
            ls0 += __shfl_xor_sync(0xffffffffu, ls0, 2);
            ls1 += __shfl_xor_sync(0xffffffffu, ls1, 1);
            ls1 += __shfl_xor_sync(0xffffffffu, ls1, 2);
            lS[mi][0] = lS[mi][0] * c0 + ls0;
            lS[mi][1] = lS[mi][1] * c1 + ls1;
            mS[mi][0] = mn0;  mS[mi][1] = mn1;
            #pragma unroll
            for (int j = 0; j < 8; j++) {
                o[mi][j][0] *= c0; o[mi][j][1] *= c0;
                o[mi][j][2] *= c1; o[mi][j][3] *= c1;
            }
            #pragma unroll
            for (int k = 0; k < 4; k++) {
                #pragma unroll
                for (int u = 0; u < 4; u++) {
                    const int jt = 2 * k + (u >> 1);
                    const int e  = (u & 1) * 2;
                    __half hx, lx, hy, ly;
                    split2h(s[mi][jt][e + 0], hx, lx);
                    split2h(s[mi][jt][e + 1], hy, ly);
                    ph[mi][k][u] = pack2h(hx, hy);
                    pq[mi][k][u] = pack2h(lx, ly);
                }
            }
        }

        #pragma unroll
        for (int d = 0; d < 4; d++) {
            #pragma unroll
            for (int k = 0; k < 4; k++) {
                uint32_t vf[4];
                uint32_t a = st + AT_PLANE + (k * 16 + lr) * AT_SROW + d * 32 + lc * 16;
                ldm_x4t(vf, a);
                #pragma unroll
                for (int mi = 0; mi < 2; mi++) {
                    mma16816(o[mi][2 * d + 0], ph[mi][k], vf[0], vf[1]);
                    mma16816(o[mi][2 * d + 0], pq[mi][k], vf[0], vf[1]);
                    mma16816(o[mi][2 * d + 1], ph[mi][k], vf[2], vf[3]);
                    mma16816(o[mi][2 * d + 1], pq[mi][k], vf[2], vf[3]);
                }
            }
        }
        __syncthreads();
    }

    const int cb = (lane & 3) * 2;
    #pragma unroll
    for (int mi = 0; mi < 2; mi++) {
        const float inv0 = 1.0f / lS[mi][0], inv1 = 1.0f / lS[mi][1];
        const int row0 = q0 + wid * 32 + mi * 16 + (lane >> 2);
        #pragma unroll
        for (int j = 0; j < 8; j++) {
            const int col = h * DK + j * 8 + cb;
            const size_t e0 = ((size_t)b * S_LEN + row0) * DMODEL + col;
            const size_t e1 = e0 + 8 * DMODEL;
            *(uint32_t*)(outA + e0) = packf2(o[mi][j][0] * inv0, o[mi][j][1] * inv0);
            *(uint32_t*)(outA + e1) = packf2(o[mi][j][2] * inv1, o[mi][j][3] * inv1);
        }
    }
}

// ============================================================================
extern "C" void kernel_launch(void* const* d_in, const int* in_sizes, int n_in,
                              void* d_out, int out_size)
{
    const float* Q  = (const float*)d_in[0];
    const float* K_ = (const float*)d_in[1];
    const float* V  = (const float*)d_in[2];
    const float* Wq = (const float*)d_in[3];
    const float* bq = (const float*)d_in[4];
    const float* Wk = (const float*)d_in[5];
    const float* bk = (const float*)d_in[6];
    const float* Wv = (const float*)d_in[7];
    const float* bv = (const float*)d_in[8];
    const float* Wo = (const float*)d_in[9];
    const float* bo = (const float*)d_in[10];

    int B = in_sizes[0] / (S_LEN * DMODEL);
    if (B > MAXB) B = MAXB;
    const int M = B * S_LEN;

    __half *aP, *wP, *qh, *ql, *kh, *vh;
    cudaGetSymbolAddress((void**)&aP, g_a16);
    cudaGetSymbolAddress((void**)&wP, g_w16);
    cudaGetSymbolAddress((void**)&qh, g_qh);
    cudaGetSymbolAddress((void**)&ql, g_ql);
    cudaGetSymbolAddress((void**)&kh, g_kh);
    cudaGetSymbolAddress((void**)&vh, g_vh);
    const size_t WSZ = (size_t)DMODEL * DMODEL;

    conv_single_w<<<1024, 256>>>(Wq, wP + 0 * WSZ);
    conv_single_w<<<1024, 256>>>(Wk, wP + 1 * WSZ);
    conv_single_w<<<1024, 256>>>(Wv, wP + 2 * WSZ);
    conv_single_w<<<1024, 256>>>(Wo, wP + 3 * WSZ);

    dim3 gg(DMODEL / 128, M / 128);

    gemm_mma<<<gg, 256, GEMM_SMEM>>>(Q,  wP + 0 * WSZ, bq, nullptr, qh, ql, M, 1, 1, 0.125f);
    gemm_mma<<<gg, 256, GEMM_SMEM>>>(K_, wP + 1 * WSZ, bk, nullptr, kh, nullptr, M, 1, 2, 1.0f);
    gemm_mma<<<gg, 256, GEMM_SMEM>>>(V,  wP + 2 * WSZ, bv, nullptr, vh, nullptr, M, 1, 2, 1.0f);

    attn_mma<<<dim3(S_LEN / 128, NHEADS, B), 128, ATT_SMEM>>>(qh, ql, kh, vh, aP);

    gemm_mma<<<gg, 256, GEMM_SMEM>>>(aP, wP + 3 * WSZ, bo, (float*)d_out, nullptr, nullptr, M, 0, 0, 1.0f);
}

// round 8
// speedup vs baseline: 5.9221x; 1.1209x over previous
#include <cuda_runtime.h>
#include <cuda_fp16.h>
#include <math.h>
#include <stdint.h>

#define S_LEN  2048
#define DMODEL 1024
#define NHEADS 16
#define DK     64
#define MAXB   2
#define MMAX   (MAXB * S_LEN)      // 4096

// ---- scratch (device globals: allocation-free) ----
__device__ __align__(16) __half g_a16[MMAX * DMODEL];              // attn-out fp16 plane
__device__ __align__(16) __half g_w16[4][DMODEL * DMODEL];         // weights single fp16 [N][K]
__device__ __align__(16) __half g_qh[MMAX * DMODEL], g_ql[MMAX * DMODEL];
__device__ __align__(16) __half g_kh[MMAX * DMODEL];
__device__ __align__(16) __half g_vh[MMAX * DMODEL];

// ============================================================================
// helpers
// ============================================================================
__device__ __forceinline__ uint32_t smem_u32(const void* p) {
    uint32_t r;
    asm("{ .reg .u64 t; cvta.to.shared.u64 t, %1; cvt.u32.u64 %0, t; }" : "=r"(r) : "l"(p));
    return r;
}
__device__ __forceinline__ void split2h(float v, __half& h, __half& l) {
    h = __float2half_rn(v);
    l = __float2half_rn(v - __half2float(h));
}
__device__ __forceinline__ uint32_t pack2h(__half a, __half b) {
    __half2 t = __halves2half2(a, b);
    return *reinterpret_cast<uint32_t*>(&t);
}
__device__ __forceinline__ uint32_t packf2(float a, float b) {
    __half2 t = __floats2half2_rn(a, b);
    return *reinterpret_cast<uint32_t*>(&t);
}
__device__ __forceinline__ void cp16(uint32_t s, const void* g) {
    asm volatile("cp.async.cg.shared.global [%0], [%1], 16;" :: "r"(s), "l"(g));
}
__device__ __forceinline__ void cp_commit() {
    asm volatile("cp.async.commit_group;");
}
template <int N> __device__ __forceinline__ void cp_wait() {
    asm volatile("cp.async.wait_group %0;" :: "n"(N));
}
__device__ __forceinline__ void ldm_x4(uint32_t* r, uint32_t a) {
    asm volatile("ldmatrix.sync.aligned.m8n8.x4.shared.b16 {%0,%1,%2,%3}, [%4];"
                 : "=r"(r[0]), "=r"(r[1]), "=r"(r[2]), "=r"(r[3]) : "r"(a));
}
__device__ __forceinline__ void ldm_x4t(uint32_t* r, uint32_t a) {
    asm volatile("ldmatrix.sync.aligned.m8n8.x4.trans.shared.b16 {%0,%1,%2,%3}, [%4];"
                 : "=r"(r[0]), "=r"(r[1]), "=r"(r[2]), "=r"(r[3]) : "r"(a));
}
__device__ __forceinline__ void mma16816(float* d, const uint32_t* a, uint32_t b0, uint32_t b1) {
    asm volatile(
        "mma.sync.aligned.m16n8k16.row.col.f32.f16.f16.f32 "
        "{%0,%1,%2,%3}, {%4,%5,%6,%7}, {%8,%9}, {%0,%1,%2,%3};"
        : "+f"(d[0]), "+f"(d[1]), "+f"(d[2]), "+f"(d[3])
        : "r"(a[0]), "r"(a[1]), "r"(a[2]), "r"(a[3]), "r"(b0), "r"(b1));
}

// ============================================================================
// All 4 weights: W[1024,1024] fp32 (k-major rows) -> transposed fp16 [N][K]
// one launch, blockIdx.y selects the weight
// ============================================================================
__global__ __launch_bounds__(256) void conv_w4(
    const float* __restrict__ W0, const float* __restrict__ W1,
    const float* __restrict__ W2, const float* __restrict__ W3,
    __half* __restrict__ dst)
{
    const int w = blockIdx.y;
    const float* W = (w == 0) ? W0 : (w == 1) ? W1 : (w == 2) ? W2 : W3;
    __half* d = dst + (size_t)w * DMODEL * DMODEL;
    int idx = blockIdx.x * 256 + threadIdx.x;
    int kg = idx >> 10, n = idx & 1023;
    int k0 = kg * 4;
    float a0 = W[(size_t)(k0 + 0) * DMODEL + n];
    float a1 = W[(size_t)(k0 + 1) * DMODEL + n];
    float a2 = W[(size_t)(k0 + 2) * DMODEL + n];
    float a3 = W[(size_t)(k0 + 3) * DMODEL + n];
    *(uint2*)(d + (size_t)n * DMODEL + k0) = make_uint2(packf2(a0, a1), packf2(a2, a3));
}

// ============================================================================
// fp16 1-pass GEMM (verified round-7): C = (A*W + bias) * scale
// aFp32=1: A fp32, converted on the fly. mode 0: fp32 C; 1: hi/lo fp16 BHSD; 2: single fp16 BHSD
// ============================================================================
#define SROW   80
#define PLANE  (128 * SROW)
#define STAGE  (2 * PLANE)
#define GEMM_SMEM (2 * STAGE)

__global__ __launch_bounds__(256) void gemm_mma(
    const void* __restrict__ aIn, const __half* __restrict__ wP,
    const float* __restrict__ bias, float* __restrict__ C,
    __half* __restrict__ outH, __half* __restrict__ outL,
    int M, int aFp32, int mode, float scale)
{
    extern __shared__ unsigned char dyn[];
    const uint32_t sbase = smem_u32(dyn);

    const int tid = threadIdx.x, lane = tid & 31, wid = tid >> 5;
    const int mw = wid >> 2, nw = wid & 3;
    const int rowBase = blockIdx.y * 128, colBase = blockIdx.x * 128;

    const __half* bW = wP + (size_t)colBase * DMODEL;

    const int r0 = tid >> 2, c0 = (tid & 3) << 4;
    const int r1 = r0 + 64;

    auto load_w = [&](int kt, int s) {
        const uint32_t sb = sbase + s * STAGE + PLANE;
        const size_t g0 = (size_t)r0 * DMODEL + kt * 32;
        const size_t g1 = (size_t)r1 * DMODEL + kt * 32;
        cp16(sb + r0 * SROW + c0, (const char*)(bW + g0) + c0);
        cp16(sb + r1 * SROW + c0, (const char*)(bW + g1) + c0);
    };
    const __half* aH = (const __half*)aIn + (size_t)rowBase * DMODEL;
    auto load_a16 = [&](int kt, int s) {
        const uint32_t sb = sbase + s * STAGE;
        const size_t g0 = (size_t)r0 * DMODEL + kt * 32;
        const size_t g1 = (size_t)r1 * DMODEL + kt * 32;
        cp16(sb + r0 * SROW + c0, (const char*)(aH + g0) + c0);
        cp16(sb + r1 * SROW + c0, (const char*)(aH + g1) + c0);
    };
    const float* aF = (const float*)aIn;
    const int fc = (tid & 3) * 8;
    float4 pf[4];
    auto ldg_a32 = [&](int kt) {
        const float* p0 = aF + (size_t)(rowBase + r0) * DMODEL + kt * 32 + fc;
        const float* p1 = aF + (size_t)(rowBase + r1) * DMODEL + kt * 32 + fc;
        pf[0] = *(const float4*)p0;  pf[1] = *(const float4*)(p0 + 4);
        pf[2] = *(const float4*)p1;  pf[3] = *(const float4*)(p1 + 4);
    };
    auto sts_a32 = [&](int s) {
        uint4 v0, v1;
        v0.x = packf2(pf[0].x, pf[0].y); v0.y = packf2(pf[0].z, pf[0].w);
        v0.z = packf2(pf[1].x, pf[1].y); v0.w = packf2(pf[1].z, pf[1].w);
        v1.x = packf2(pf[2].x, pf[2].y); v1.y = packf2(pf[2].z, pf[2].w);
        v1.z = packf2(pf[3].x, pf[3].y); v1.w = packf2(pf[3].z, pf[3].w);
        *(uint4*)(dyn + s * STAGE + r0 * SROW + c0) = v0;
        *(uint4*)(dyn + s * STAGE + r1 * SROW + c0) = v1;
    };

    float acc[4][4][4] = {};
    const int lr = lane & 15, lc = lane >> 4;

    if (aFp32) {
        ldg_a32(0); sts_a32(0); ldg_a32(1);
    } else {
        load_a16(0, 0);
    }
    load_w(0, 0);
    cp_commit();

    const int NIT = DMODEL / 32;
    for (int kt = 0; kt < NIT; kt++) {
        const int s = kt & 1;
        if (kt + 1 < NIT) {
            load_w(kt + 1, s ^ 1);
            if (!aFp32) load_a16(kt + 1, s ^ 1);
        }
        cp_commit();
        cp_wait<1>();
        __syncthreads();

        const uint32_t sb = sbase + s * STAGE;
        #pragma unroll
        for (int kk = 0; kk < 2; kk++) {
            uint32_t ah[4][4], bh[2][4];
            #pragma unroll
            for (int mi = 0; mi < 4; mi++) {
                uint32_t ra = sb + (mw * 64 + mi * 16 + lr) * SROW + kk * 32 + lc * 16;
                ldm_x4(ah[mi], ra);
            }
            #pragma unroll
            for (int ni = 0; ni < 2; ni++) {
                uint32_t rb = sb + PLANE + (nw * 32 + ni * 16 + lr) * SROW + kk * 32 + lc * 16;
                ldm_x4(bh[ni], rb);
            }
            #pragma unroll
            for (int mi = 0; mi < 4; mi++) {
                #pragma unroll
                for (int n8 = 0; n8 < 4; n8++) {
                    const int ni = n8 >> 1, hf = n8 & 1;
                    mma16816(acc[mi][n8], ah[mi], bh[ni][hf], bh[ni][hf + 2]);
                }
            }
        }
        if (aFp32 && kt + 1 < NIT) {
            sts_a32(s ^ 1);
            if (kt + 2 < NIT) ldg_a32(kt + 2);
        }
        __syncthreads();
    }

    const int wr = rowBase + mw * 64, wc = colBase + nw * 32;
    #pragma unroll
    for (int mi = 0; mi < 4; mi++) {
        #pragma unroll
        for (int n8 = 0; n8 < 4; n8++) {
            const int col = wc + n8 * 8 + (lane & 3) * 2;
            const float b0 = bias[col], b1 = bias[col + 1];
            #pragma unroll
            for (int h = 0; h < 2; h++) {
                const int row = wr + mi * 16 + (lane >> 2) + 8 * h;
                float ox = (acc[mi][n8][2 * h + 0] + b0) * scale;
                float oy = (acc[mi][n8][2 * h + 1] + b1) * scale;
                if (mode == 0) {
                    float2 o; o.x = ox; o.y = oy;
                    *(float2*)&C[(size_t)row * DMODEL + col] = o;
                } else {
                    int bb = row >> 11, ss = row & 2047;
                    int hh = col >> 6, dd = col & 63;
                    size_t e = ((size_t)(bb * NHEADS + hh) * S_LEN + ss) * DK + dd;
                    if (mode == 1) {
                        __half hx, lx, hy, ly;
                        split2h(ox, hx, lx); split2h(oy, hy, ly);
                        *(uint32_t*)(outH + e) = pack2h(hx, hy);
                        *(uint32_t*)(outL + e) = pack2h(lx, ly);
                    } else {
                        *(uint32_t*)(outH + e) = packf2(ox, oy);
                    }
                }
            }
        }
    }
}

// ============================================================================
// FA2 attention: fp16, Q hi/lo 2-pass QK^T, single-pass P·V (P fp16).
// CTA: 128 q-rows, 4 warps x 32 q-rows. Writes single fp16 plane for O-proj.
// ============================================================================
#define AT_SROW  144
#define AT_PLANE (64 * AT_SROW)
#define AT_STAGE (2 * AT_PLANE)
#define ATT_SMEM (2 * AT_STAGE)

__global__ __launch_bounds__(128) void attn_mma(
    const __half* __restrict__ qhG, const __half* __restrict__ qlG,
    const __half* __restrict__ khG, const __half* __restrict__ vhG,
    __half* __restrict__ outA)
{
    extern __shared__ unsigned char dyn[];
    const uint32_t sb = smem_u32(dyn);
    const int tid = threadIdx.x, lane = tid & 31, wid = tid >> 5;
    const int q0 = blockIdx.x * 128, h = blockIdx.y, b = blockIdx.z;
    const size_t hb = (size_t)(b * NHEADS + h) * S_LEN * DK;

    const char* qhB = (const char*)(qhG + hb);
    const char* qlB = (const char*)(qlG + hb);
    const char* khB = (const char*)(khG + hb);
    const char* vhB = (const char*)(vhG + hb);

    #pragma unroll
    for (int i = 0; i < 16; i++) {
        int cid = tid + 128 * i;
        int pl = cid >> 10;
        int r  = (cid >> 3) & 127;
        int c  = (cid & 7) * 16;
        const char* g = (pl ? qlB : qhB) + (size_t)(q0 + r) * (DK * 2) + c;
        cp16(sb + pl * (128 * AT_SROW) + r * AT_SROW + c, g);
    }
    cp_commit(); cp_wait<0>(); __syncthreads();

    const int lr = lane & 15, lc = lane >> 4;
    uint32_t qfh[2][4][4], qfl[2][4][4];
    #pragma unroll
    for (int mi = 0; mi < 2; mi++) {
        #pragma unroll
        for (int ks = 0; ks < 4; ks++) {
            uint32_t a = sb + (wid * 32 + mi * 16 + lr) * AT_SROW + ks * 32 + lc * 16;
            ldm_x4(qfh[mi][ks], a);
            ldm_x4(qfl[mi][ks], a + 128 * AT_SROW);
        }
    }
    __syncthreads();

    float o[2][8][4] = {};
    float mS[2][2] = {{-1e30f, -1e30f}, {-1e30f, -1e30f}};
    float lS[2][2] = {};

    auto load_kv = [&](int t, int s) {
        const uint32_t st = sb + s * AT_STAGE;
        #pragma unroll
        for (int i = 0; i < 8; i++) {
            int cid = tid + 128 * i;
            int pl = cid >> 9;
            int r  = (cid >> 3) & 63;
            int c  = (cid & 7) * 16;
            const char* g = (pl == 0) ? khB : vhB;
            g += (size_t)(t * 64 + r) * (DK * 2) + c;
            cp16(st + pl * AT_PLANE + r * AT_SROW + c, g);
        }
    };

    load_kv(0, 0);
    cp_commit();

    const int NT = S_LEN / 64;
    for (int t = 0; t < NT; t++) {
        if (t + 1 < NT) load_kv(t + 1, (t + 1) & 1);
        cp_commit();
        cp_wait<1>();
        __syncthreads();
        const uint32_t st = sb + (t & 1) * AT_STAGE;

        // ---- S = Q K^T (Q hi/lo, K single) ----
        float s[2][8][4] = {};
        #pragma unroll
        for (int g = 0; g < 4; g++) {
            #pragma unroll
            for (int ks = 0; ks < 4; ks++) {
                uint32_t kf[4];
                uint32_t a = st + (g * 16 + lr) * AT_SROW + ks * 32 + lc * 16;
                ldm_x4(kf, a);
                #pragma unroll
                for (int mi = 0; mi < 2; mi++) {
                    #pragma unroll
                    for (int hf = 0; hf < 2; hf++) {
                        mma16816(s[mi][2 * g + hf], qfh[mi][ks], kf[hf], kf[hf + 2]);
                        mma16816(s[mi][2 * g + hf], qfl[mi][ks], kf[hf], kf[hf + 2]);
                    }
                }
            }
        }

        // ---- online softmax + P fragments (single fp16) ----
        uint32_t ph[2][4][4];
        #pragma unroll
        for (int mi = 0; mi < 2; mi++) {
            float mx0 = -1e30f, mx1 = -1e30f;
            #pragma unroll
            for (int j = 0; j < 8; j++) {
                mx0 = fmaxf(mx0, fmaxf(s[mi][j][0], s[mi][j][1]));
                mx1 = fmaxf(mx1, fmaxf(s[mi][j][2], s[mi][j][3]));
            }
            mx0 = fmaxf(mx0, __shfl_xor_sync(0xffffffffu, mx0, 1));
            mx0 = fmaxf(mx0, __shfl_xor_sync(0xffffffffu, mx0, 2));
            mx1 = fmaxf(mx1, __shfl_xor_sync(0xffffffffu, mx1, 1));
            mx1 = fmaxf(mx1, __shfl_xor_sync(0xffffffffu, mx1, 2));
            const float mn0 = fmaxf(mS[mi][0], mx0), mn1 = fmaxf(mS[mi][1], mx1);
            const float c0 = __expf(mS[mi][0] - mn0), c1 = __expf(mS[mi][1] - mn1);
            float ls0 = 0.f, ls1 = 0.f;
            #pragma unroll
            for (int j = 0; j < 8; j++) {
                s[mi][j][0] = __expf(s[mi][j][0] - mn0);
                s[mi][j][1] = __expf(s[mi][j][1] - mn0);
                s[mi][j][2] = __expf(s[mi][j][2] - mn1);
                s[mi][j][3] = __expf(s[mi][j][3] - mn1);
                ls0 += s[mi][j][0] + s[mi][j][1];
                ls1 += s[mi][j][2] + s[mi][j][3];
            }
            ls0 += __shfl_xor_sync(0xffffffffu, ls0, 1);
            ls0 += __shfl_xor_sync(0xffffffffu, ls0, 2);
            ls1 += __shfl_xor_sync(0xffffffffu, ls1, 1);
            ls1 += __shfl_xor_sync(0xffffffffu, ls1, 2);
            lS[mi][0] = lS[mi][0] * c0 + ls0;
            lS[mi][1] = lS[mi][1] * c1 + ls1;
            mS[mi][0] = mn0;  mS[mi][1] = mn1;
            #pragma unroll
            for (int j = 0; j < 8; j++) {
                o[mi][j][0] *= c0; o[mi][j][1] *= c0;
                o[mi][j][2] *= c1; o[mi][j][3] *= c1;
            }
            // P -> A fragments, verified round-4 mapping (hi only)
            #pragma unroll
            for (int k = 0; k < 4; k++) {
                #pragma unroll
                for (int u = 0; u < 4; u++) {
                    const int jt = 2 * k + (u >> 1);
                    const int e  = (u & 1) * 2;
                    ph[mi][k][u] = packf2(s[mi][jt][e + 0], s[mi][jt][e + 1]);
                }
            }
        }

        // ---- O += P V (both single fp16), V via ldmatrix.trans ----
        #pragma unroll
        for (int d = 0; d < 4; d++) {
            #pragma unroll
            for (int k = 0; k < 4; k++) {
                uint32_t vf[4];
                uint32_t a = st + AT_PLANE + (k * 16 + lr) * AT_SROW + d * 32 + lc * 16;
                ldm_x4t(vf, a);
                #pragma unroll
                for (int mi = 0; mi < 2; mi++) {
                    mma16816(o[mi][2 * d + 0], ph[mi][k], vf[0], vf[1]);
                    mma16816(o[mi][2 * d + 1], ph[mi][k], vf[2], vf[3]);
                }
            }
        }
        __syncthreads();
    }

    const int cb = (lane & 3) * 2;
    #pragma unroll
    for (int mi = 0; mi < 2; mi++) {
        const float inv0 = 1.0f / lS[mi][0], inv1 = 1.0f / lS[mi][1];
        const int row0 = q0 + wid * 32 + mi * 16 + (lane >> 2);
        #pragma unroll
        for (int j = 0; j < 8; j++) {
            const int col = h * DK + j * 8 + cb;
            const size_t e0 = ((size_t)b * S_LEN + row0) * DMODEL + col;
            const size_t e1 = e0 + 8 * DMODEL;
            *(uint32_t*)(outA + e0) = packf2(o[mi][j][0] * inv0, o[mi][j][1] * inv0);
            *(uint32_t*)(outA + e1) = packf2(o[mi][j][2] * inv1, o[mi][j][3] * inv1);
        }
    }
}

// ============================================================================
extern "C" void kernel_launch(void* const* d_in, const int* in_sizes, int n_in,
                              void* d_out, int out_size)
{
    const float* Q  = (const float*)d_in[0];
    const float* K_ = (const float*)d_in[1];
    const float* V  = (const float*)d_in[2];
    const float* Wq = (const float*)d_in[3];
    const float* bq = (const float*)d_in[4];
    const float* Wk = (const float*)d_in[5];
    const float* bk = (const float*)d_in[6];
    const float* Wv = (const float*)d_in[7];
    const float* bv = (const float*)d_in[8];
    const float* Wo = (const float*)d_in[9];
    const float* bo = (const float*)d_in[10];

    int B = in_sizes[0] / (S_LEN * DMODEL);
    if (B > MAXB) B = MAXB;
    const int M = B * S_LEN;

    __half *aP, *wP, *qh, *ql, *kh, *vh;
    cudaGetSymbolAddress((void**)&aP, g_a16);
    cudaGetSymbolAddress((void**)&wP, g_w16);
    cudaGetSymbolAddress((void**)&qh, g_qh);
    cudaGetSymbolAddress((void**)&ql, g_ql);
    cudaGetSymbolAddress((void**)&kh, g_kh);
    cudaGetSymbolAddress((void**)&vh, g_vh);
    const size_t WSZ = (size_t)DMODEL * DMODEL;

    conv_w4<<<dim3(1024, 4), 256>>>(Wq, Wk, Wv, Wo, wP);

    dim3 gg(DMODEL / 128, M / 128);

    gemm_mma<<<gg, 256, GEMM_SMEM>>>(Q,  wP + 0 * WSZ, bq, nullptr, qh, ql, M, 1, 1, 0.125f);
    gemm_mma<<<gg, 256, GEMM_SMEM>>>(K_, wP + 1 * WSZ, bk, nullptr, kh, nullptr, M, 1, 2, 1.0f);
    gemm_mma<<<gg, 256, GEMM_SMEM>>>(V,  wP + 2 * WSZ, bv, nullptr, vh, nullptr, M, 1, 2, 1.0f);

    attn_mma<<<dim3(S_LEN / 128, NHEADS, B), 128, ATT_SMEM>>>(qh, ql, kh, vh, aP);

    gemm_mma<<<gg, 256, GEMM_SMEM>>>(aP, wP + 3 * WSZ, bo, (float*)d_out, nullptr, nullptr, M, 0, 0, 1.0f);
}

// round 9
// speedup vs baseline: 5.9527x; 1.0052x over previous
#include <cuda_runtime.h>
#include <cuda_fp16.h>
#include <math.h>
#include <stdint.h>

#define S_LEN  2048
#define DMODEL 1024
#define NHEADS 16
#define DK     64
#define MAXB   2
#define MMAX   (MAXB * S_LEN)      // 4096

// ---- scratch (device globals: allocation-free) ----
__device__ __align__(16) __half g_a16[MMAX * DMODEL];              // attn-out fp16 plane
__device__ __align__(16) __half g_w16[4][DMODEL * DMODEL];         // weights single fp16 [N][K]
__device__ __align__(16) __half g_qh[MMAX * DMODEL], g_ql[MMAX * DMODEL];
__device__ __align__(16) __half g_kh[MMAX * DMODEL];
__device__ __align__(16) __half g_vh[MMAX * DMODEL];

// ============================================================================
// helpers
// ============================================================================
__device__ __forceinline__ uint32_t smem_u32(const void* p) {
    uint32_t r;
    asm("{ .reg .u64 t; cvta.to.shared.u64 t, %1; cvt.u32.u64 %0, t; }" : "=r"(r) : "l"(p));
    return r;
}
__device__ __forceinline__ void split2h(float v, __half& h, __half& l) {
    h = __float2half_rn(v);
    l = __float2half_rn(v - __half2float(h));
}
__device__ __forceinline__ uint32_t pack2h(__half a, __half b) {
    __half2 t = __halves2half2(a, b);
    return *reinterpret_cast<uint32_t*>(&t);
}
__device__ __forceinline__ uint32_t packf2(float a, float b) {
    __half2 t = __floats2half2_rn(a, b);
    return *reinterpret_cast<uint32_t*>(&t);
}
__device__ __forceinline__ void cp16(uint32_t s, const void* g) {
    asm volatile("cp.async.cg.shared.global [%0], [%1], 16;" :: "r"(s), "l"(g));
}
__device__ __forceinline__ void cp_commit() {
    asm volatile("cp.async.commit_group;");
}
template <int N> __device__ __forceinline__ void cp_wait() {
    asm volatile("cp.async.wait_group %0;" :: "n"(N));
}
__device__ __forceinline__ void ldm_x4(uint32_t* r, uint32_t a) {
    asm volatile("ldmatrix.sync.aligned.m8n8.x4.shared.b16 {%0,%1,%2,%3}, [%4];"
                 : "=r"(r[0]), "=r"(r[1]), "=r"(r[2]), "=r"(r[3]) : "r"(a));
}
__device__ __forceinline__ void ldm_x4t(uint32_t* r, uint32_t a) {
    asm volatile("ldmatrix.sync.aligned.m8n8.x4.trans.shared.b16 {%0,%1,%2,%3}, [%4];"
                 : "=r"(r[0]), "=r"(r[1]), "=r"(r[2]), "=r"(r[3]) : "r"(a));
}
__device__ __forceinline__ void mma16816(float* d, const uint32_t* a, uint32_t b0, uint32_t b1) {
    asm volatile(
        "mma.sync.aligned.m16n8k16.row.col.f32.f16.f16.f32 "
        "{%0,%1,%2,%3}, {%4,%5,%6,%7}, {%8,%9}, {%0,%1,%2,%3};"
        : "+f"(d[0]), "+f"(d[1]), "+f"(d[2]), "+f"(d[3])
        : "r"(a[0]), "r"(a[1]), "r"(a[2]), "r"(a[3]), "r"(b0), "r"(b1));
}

// ============================================================================
// All 4 weights: fp32 [K,N] -> transposed fp16 [N][K], one launch
// ============================================================================
__global__ __launch_bounds__(256) void conv_w4(
    const float* __restrict__ W0, const float* __restrict__ W1,
    const float* __restrict__ W2, const float* __restrict__ W3,
    __half* __restrict__ dst)
{
    const int w = blockIdx.y;
    const float* W = (w == 0) ? W0 : (w == 1) ? W1 : (w == 2) ? W2 : W3;
    __half* d = dst + (size_t)w * DMODEL * DMODEL;
    int idx = blockIdx.x * 256 + threadIdx.x;
    int kg = idx >> 10, n = idx & 1023;
    int k0 = kg * 4;
    float a0 = W[(size_t)(k0 + 0) * DMODEL + n];
    float a1 = W[(size_t)(k0 + 1) * DMODEL + n];
    float a2 = W[(size_t)(k0 + 2) * DMODEL + n];
    float a3 = W[(size_t)(k0 + 3) * DMODEL + n];
    *(uint2*)(d + (size_t)n * DMODEL + k0) = make_uint2(packf2(a0, a1), packf2(a2, a3));
}

// ============================================================================
// fp16 1-pass GEMM, 128 threads, 4 warps, warp tile 64x64 (mi4 x n8x8).
// Single __syncthreads per K-iteration, double-buffered cp.async.
// AFP32: A is fp32, converted on the fly via LDG->cvt->STS.
// mode 0: fp32 C; 1: hi/lo fp16 BHSD; 2: single fp16 BHSD
// ============================================================================
#define SROW   80
#define PLANE  (128 * SROW)
#define STAGE  (2 * PLANE)
#define GEMM_SMEM (2 * STAGE)   // 40960

template<int AFP32>
__global__ __launch_bounds__(128) void gemm_mma(
    const void* __restrict__ aIn, const __half* __restrict__ wP,
    const float* __restrict__ bias, float* __restrict__ C,
    __half* __restrict__ outH, __half* __restrict__ outL,
    int M, int mode, float scale)
{
    extern __shared__ unsigned char dyn[];
    const uint32_t sbase = smem_u32(dyn);

    const int tid = threadIdx.x, lane = tid & 31, wid = tid >> 5;   // 4 warps
    const int mw = wid >> 1, nw = wid & 1;                          // 2x2 warp grid
    const int rowBase = blockIdx.y * 128, colBase = blockIdx.x * 128;

    const __half* bW = wP + (size_t)colBase * DMODEL;

    const int cr = tid >> 2, c0 = (tid & 3) << 4;   // 4 chunk-rows per thread

    auto load_w = [&](int kt, int s) {
        const uint32_t sb = sbase + s * STAGE + PLANE;
        #pragma unroll
        for (int i = 0; i < 4; i++) {
            int r = cr + 32 * i;
            cp16(sb + r * SROW + c0, (const char*)(bW + (size_t)r * DMODEL + kt * 32) + c0);
        }
    };
    const __half* aH = (const __half*)aIn + (size_t)rowBase * DMODEL;
    auto load_a16 = [&](int kt, int s) {
        const uint32_t sb = sbase + s * STAGE;
        #pragma unroll
        for (int i = 0; i < 4; i++) {
            int r = cr + 32 * i;
            cp16(sb + r * SROW + c0, (const char*)(aH + (size_t)r * DMODEL + kt * 32) + c0);
        }
    };
    const float* aF = (const float*)aIn;
    const int fc = (tid & 3) * 8;
    float4 pf[8];
    auto ldg_a32 = [&](int kt) {
        #pragma unroll
        for (int i = 0; i < 4; i++) {
            const float* p = aF + (size_t)(rowBase + cr + 32 * i) * DMODEL + kt * 32 + fc;
            pf[2 * i]     = *(const float4*)p;
            pf[2 * i + 1] = *(const float4*)(p + 4);
        }
    };
    auto sts_a32 = [&](int s) {
        #pragma unroll
        for (int i = 0; i < 4; i++) {
            uint4 v;
            v.x = packf2(pf[2 * i].x,     pf[2 * i].y);
            v.y = packf2(pf[2 * i].z,     pf[2 * i].w);
            v.z = packf2(pf[2 * i + 1].x, pf[2 * i + 1].y);
            v.w = packf2(pf[2 * i + 1].z, pf[2 * i + 1].w);
            *(uint4*)(dyn + s * STAGE + (cr + 32 * i) * SROW + c0) = v;
        }
    };

    float acc[4][8][4] = {};
    const int lr = lane & 15, lc = lane >> 4;

    if (AFP32) {
        ldg_a32(0); sts_a32(0); ldg_a32(1);
    } else {
        load_a16(0, 0);
    }
    load_w(0, 0);
    cp_commit();

    const int NIT = DMODEL / 32;
    for (int kt = 0; kt < NIT; kt++) {
        const int s = kt & 1;
        cp_wait<0>();
        __syncthreads();                       // stage s ready; stage s^1 free
        if (kt + 1 < NIT) {
            load_w(kt + 1, s ^ 1);
            if (!AFP32) load_a16(kt + 1, s ^ 1);
        }
        if (AFP32 && kt + 1 < NIT) {
            sts_a32(s ^ 1);
            if (kt + 2 < NIT) ldg_a32(kt + 2);
        }
        cp_commit();

        const uint32_t sb = sbase + s * STAGE;
        #pragma unroll
        for (int kk = 0; kk < 2; kk++) {
            uint32_t ah[4][4], bh[4][4];
            #pragma unroll
            for (int mi = 0; mi < 4; mi++)
                ldm_x4(ah[mi], sb + (mw * 64 + mi * 16 + lr) * SROW + kk * 32 + lc * 16);
            #pragma unroll
            for (int ni = 0; ni < 4; ni++)
                ldm_x4(bh[ni], sb + PLANE + (nw * 64 + ni * 16 + lr) * SROW + kk * 32 + lc * 16);
            #pragma unroll
            for (int mi = 0; mi < 4; mi++) {
                #pragma unroll
                for (int n8 = 0; n8 < 8; n8++) {
                    const int ni = n8 >> 1, hf = n8 & 1;
                    mma16816(acc[mi][n8], ah[mi], bh[ni][hf], bh[ni][hf + 2]);
                }
            }
        }
    }

    const int wr = rowBase + mw * 64, wc = colBase + nw * 64;
    #pragma unroll
    for (int mi = 0; mi < 4; mi++) {
        #pragma unroll
        for (int n8 = 0; n8 < 8; n8++) {
            const int col = wc + n8 * 8 + (lane & 3) * 2;
            const float b0 = bias[col], b1 = bias[col + 1];
            #pragma unroll
            for (int h = 0; h < 2; h++) {
                const int row = wr + mi * 16 + (lane >> 2) + 8 * h;
                float ox = (acc[mi][n8][2 * h + 0] + b0) * scale;
                float oy = (acc[mi][n8][2 * h + 1] + b1) * scale;
                if (mode == 0) {
                    float2 o; o.x = ox; o.y = oy;
                    *(float2*)&C[(size_t)row * DMODEL + col] = o;
                } else {
                    int bb = row >> 11, ss = row & 2047;
                    int hh = col >> 6, dd = col & 63;
                    size_t e = ((size_t)(bb * NHEADS + hh) * S_LEN + ss) * DK + dd;
                    if (mode == 1) {
                        __half hx, lx, hy, ly;
                        split2h(ox, hx, lx); split2h(oy, hy, ly);
                        *(uint32_t*)(outH + e) = pack2h(hx, hy);
                        *(uint32_t*)(outL + e) = pack2h(lx, ly);
                    } else {
                        *(uint32_t*)(outH + e) = packf2(ox, oy);
                    }
                }
            }
        }
    }
}

// ============================================================================
// FA2 attention (verified round-8, unchanged): fp16, Q hi/lo 2-pass QK^T,
// single-pass P·V. CTA: 128 q-rows, 4 warps x 32 q-rows.
// ============================================================================
#define AT_SROW  144
#define AT_PLANE (64 * AT_SROW)
#define AT_STAGE (2 * AT_PLANE)
#define ATT_SMEM (2 * AT_STAGE)

__global__ __launch_bounds__(128) void attn_mma(
    const __half* __restrict__ qhG, const __half* __restrict__ qlG,
    const __half* __restrict__ khG, const __half* __restrict__ vhG,
    __half* __restrict__ outA)
{
    extern __shared__ unsigned char dyn[];
    const uint32_t sb = smem_u32(dyn);
    const int tid = threadIdx.x, lane = tid & 31, wid = tid >> 5;
    const int q0 = blockIdx.x * 128, h = blockIdx.y, b = blockIdx.z;
    const size_t hb = (size_t)(b * NHEADS + h) * S_LEN * DK;

    const char* qhB = (const char*)(qhG + hb);
    const char* qlB = (const char*)(qlG + hb);
    const char* khB = (const char*)(khG + hb);
    const char* vhB = (const char*)(vhG + hb);

    #pragma unroll
    for (int i = 0; i < 16; i++) {
        int cid = tid + 128 * i;
        int pl = cid >> 10;
        int r  = (cid >> 3) & 127;
        int c  = (cid & 7) * 16;
        const char* g = (pl ? qlB : qhB) + (size_t)(q0 + r) * (DK * 2) + c;
        cp16(sb + pl * (128 * AT_SROW) + r * AT_SROW + c, g);
    }
    cp_commit(); cp_wait<0>(); __syncthreads();

    const int lr = lane & 15, lc = lane >> 4;
    uint32_t qfh[2][4][4], qfl[2][4][4];
    #pragma unroll
    for (int mi = 0; mi < 2; mi++) {
        #pragma unroll
        for (int ks = 0; ks < 4; ks++) {
            uint32_t a = sb + (wid * 32 + mi * 16 + lr) * AT_SROW + ks * 32 + lc * 16;
            ldm_x4(qfh[mi][ks], a);
            ldm_x4(qfl[mi][ks], a + 128 * AT_SROW);
        }
    }
    __syncthreads();

    float o[2][8][4] = {};
    float mS[2][2] = {{-1e30f, -1e30f}, {-1e30f, -1e30f}};
    float lS[2][2] = {};

    auto load_kv = [&](int t, int s) {
        const uint32_t st = sb + s * AT_STAGE;
        #pragma unroll
        for (int i = 0; i < 8; i++) {
            int cid = tid + 128 * i;
            int pl = cid >> 9;
            int r  = (cid >> 3) & 63;
            int c  = (cid & 7) * 16;
            const char* g = (pl == 0) ? khB : vhB;
            g += (size_t)(t * 64 + r) * (DK * 2) + c;
            cp16(st + pl * AT_PLANE + r * AT_SROW + c, g);
        }
    };

    load_kv(0, 0);
    cp_commit();

    const int NT = S_LEN / 64;
    for (int t = 0; t < NT; t++) {
        if (t + 1 < NT) load_kv(t + 1, (t + 1) & 1);
        cp_commit();
        cp_wait<1>();
        __syncthreads();
        const uint32_t st = sb + (t & 1) * AT_STAGE;

        float s[2][8][4] = {};
        #pragma unroll
        for (int g = 0; g < 4; g++) {
            #pragma unroll
            for (int ks = 0; ks < 4; ks++) {
                uint32_t kf[4];
                uint32_t a = st + (g * 16 + lr) * AT_SROW + ks * 32 + lc * 16;
                ldm_x4(kf, a);
                #pragma unroll
                for (int mi = 0; mi < 2; mi++) {
                    #pragma unroll
                    for (int hf = 0; hf < 2; hf++) {
                        mma16816(s[mi][2 * g + hf], qfh[mi][ks], kf[hf], kf[hf + 2]);
                        mma16816(s[mi][2 * g + hf], qfl[mi][ks], kf[hf], kf[hf + 2]);
                    }
                }
            }
        }

        uint32_t ph[2][4][4];
        #pragma unroll
        for (int mi = 0; mi < 2; mi++) {
            float mx0 = -1e30f, mx1 = -1e30f;
            #pragma unroll
            for (int j = 0; j < 8; j++) {
                mx0 = fmaxf(mx0, fmaxf(s[mi][j][0], s[mi][j][1]));
                mx1 = fmaxf(mx1, fmaxf(s[mi][j][2], s[mi][j][3]));
            }
            mx0 = fmaxf(mx0, __shfl_xor_sync(0xffffffffu, mx0, 1));
            mx0 = fmaxf(mx0, __shfl_xor_sync(0xffffffffu, mx0, 2));
            mx1 = fmaxf(mx1, __shfl_xor_sync(0xffffffffu, mx1, 1));
            mx1 = fmaxf(mx1, __shfl_xor_sync(0xffffffffu, mx1, 2));
            const float mn0 = fmaxf(mS[mi][0], mx0), mn1 = fmaxf(mS[mi][1], mx1);
            const float c0 = __expf(mS[mi][0] - mn0), c1 = __expf(mS[mi][1] - mn1);
            float ls0 = 0.f, ls1 = 0.f;
            #pragma unroll
            for (int j = 0; j < 8; j++) {
                s[mi][j][0] = __expf(s[mi][j][0] - mn0);
                s[mi][j][1] = __expf(s[mi][j][1] - mn0);
                s[mi][j][2] = __expf(s[mi][j][2] - mn1);
                s[mi][j][3] = __expf(s[mi][j][3] - mn1);
                ls0 += s[mi][j][0] + s[mi][j][1];
                ls1 += s[mi][j][2] + s[mi][j][3];
            }
            ls0 += __shfl_xor_sync(0xffffffffu, ls0, 1);
            ls0 += __shfl_xor_sync(0xffffffffu, ls0, 2);
            ls1 += __shfl_xor_sync(0xffffffffu, ls1, 1);
            ls1 += __shfl_xor_sync(0xffffffffu, ls1, 2);
            lS[mi][0] = lS[mi][0] * c0 + ls0;
            lS[mi][1] = lS[mi][1] * c1 + ls1;
            mS[mi][0] = mn0;  mS[mi][1] = mn1;
            #pragma unroll
            for (int j = 0; j < 8; j++) {
                o[mi][j][0] *= c0; o[mi][j][1] *= c0;
                o[mi][j][2] *= c1; o[mi][j][3] *= c1;
            }
            #pragma unroll
            for (int k = 0; k < 4; k++) {
                #pragma unroll
                for (int u = 0; u < 4; u++) {
                    const int jt = 2 * k + (u >> 1);
                    const int e  = (u & 1) * 2;
                    ph[mi][k][u] = packf2(s[mi][jt][e + 0], s[mi][jt][e + 1]);
                }
            }
        }

        #pragma unroll
        for (int d = 0; d < 4; d++) {
            #pragma unroll
            for (int k = 0; k < 4; k++) {
                uint32_t vf[4];
                uint32_t a = st + AT_PLANE + (k * 16 + lr) * AT_SROW + d * 32 + lc * 16;
                ldm_x4t(vf, a);
                #pragma unroll
                for (int mi = 0; mi < 2; mi++) {
                    mma16816(o[mi][2 * d + 0], ph[mi][k], vf[0], vf[1]);
                    mma16816(o[mi][2 * d + 1], ph[mi][k], vf[2], vf[3]);
                }
            }
        }
        __syncthreads();
    }

    const int cb = (lane & 3) * 2;
    #pragma unroll
    for (int mi = 0; mi < 2; mi++) {
        const float inv0 = 1.0f / lS[mi][0], inv1 = 1.0f / lS[mi][1];
        const int row0 = q0 + wid * 32 + mi * 16 + (lane >> 2);
        #pragma unroll
        for (int j = 0; j < 8; j++) {
            const int col = h * DK + j * 8 + cb;
            const size_t e0 = ((size_t)b * S_LEN + row0) * DMODEL + col;
            const size_t e1 = e0 + 8 * DMODEL;
            *(uint32_t*)(outA + e0) = packf2(o[mi][j][0] * inv0, o[mi][j][1] * inv0);
            *(uint32_t*)(outA + e1) = packf2(o[mi][j][2] * inv1, o[mi][j][3] * inv1);
        }
    }
}

// ============================================================================
extern "C" void kernel_launch(void* const* d_in, const int* in_sizes, int n_in,
                              void* d_out, int out_size)
{
    const float* Q  = (const float*)d_in[0];
    const float* K_ = (const float*)d_in[1];
    const float* V  = (const float*)d_in[2];
    const float* Wq = (const float*)d_in[3];
    const float* bq = (const float*)d_in[4];
    const float* Wk = (const float*)d_in[5];
    const float* bk = (const float*)d_in[6];
    const float* Wv = (const float*)d_in[7];
    const float* bv = (const float*)d_in[8];
    const float* Wo = (const float*)d_in[9];
    const float* bo = (const float*)d_in[10];

    int B = in_sizes[0] / (S_LEN * DMODEL);
    if (B > MAXB) B = MAXB;
    const int M = B * S_LEN;

    __half *aP, *wP, *qh, *ql, *kh, *vh;
    cudaGetSymbolAddress((void**)&aP, g_a16);
    cudaGetSymbolAddress((void**)&wP, g_w16);
    cudaGetSymbolAddress((void**)&qh, g_qh);
    cudaGetSymbolAddress((void**)&ql, g_ql);
    cudaGetSymbolAddress((void**)&kh, g_kh);
    cudaGetSymbolAddress((void**)&vh, g_vh);
    const size_t WSZ = (size_t)DMODEL * DMODEL;

    conv_w4<<<dim3(1024, 4), 256>>>(Wq, Wk, Wv, Wo, wP);

    dim3 gg(DMODEL / 128, M / 128);

    gemm_mma<1><<<gg, 128, GEMM_SMEM>>>(Q,  wP + 0 * WSZ, bq, nullptr, qh, ql, M, 1, 0.125f);
    gemm_mma<1><<<gg, 128, GEMM_SMEM>>>(K_, wP + 1 * WSZ, bk, nullptr, kh, nullptr, M, 2, 1.0f);
    gemm_mma<1><<<gg, 128, GEMM_SMEM>>>(V,  wP + 2 * WSZ, bv, nullptr, vh, nullptr, M, 2, 1.0f);

    attn_mma<<<dim3(S_LEN / 128, NHEADS, B), 128, ATT_SMEM>>>(qh, ql, kh, vh, aP);

    gemm_mma<0><<<gg, 128, GEMM_SMEM>>>(aP, wP + 3 * WSZ, bo, (float*)d_out, nullptr, nullptr, M, 0, 1.0f);
}

// round 10
// speedup vs baseline: 6.1508x; 1.0333x over previous
#include <cuda_runtime.h>
#include <cuda_fp16.h>
#include <math.h>
#include <stdint.h>

#define S_LEN  2048
#define DMODEL 1024
#define NHEADS 16
#define DK     64
#define MAXB   2
#define MMAX   (MAXB * S_LEN)      // 4096

// ---- scratch (device globals: allocation-free) ----
__device__ __align__(16) __half g_x16[3][MMAX * DMODEL];           // Q/K/V inputs fp16
__device__ __align__(16) __half g_a16[MMAX * DMODEL];              // attn-out fp16 plane
__device__ __align__(16) __half g_w16[4][DMODEL * DMODEL];         // weights fp16 [N][K]
__device__ __align__(16) __half g_qh[MMAX * DMODEL], g_ql[MMAX * DMODEL];
__device__ __align__(16) __half g_kh[MMAX * DMODEL];
__device__ __align__(16) __half g_vh[MMAX * DMODEL];

// ============================================================================
// helpers
// ============================================================================
__device__ __forceinline__ uint32_t smem_u32(const void* p) {
    uint32_t r;
    asm("{ .reg .u64 t; cvta.to.shared.u64 t, %1; cvt.u32.u64 %0, t; }" : "=r"(r) : "l"(p));
    return r;
}
__device__ __forceinline__ void split2h(float v, __half& h, __half& l) {
    h = __float2half_rn(v);
    l = __float2half_rn(v - __half2float(h));
}
__device__ __forceinline__ uint32_t pack2h(__half a, __half b) {
    __half2 t = __halves2half2(a, b);
    return *reinterpret_cast<uint32_t*>(&t);
}
__device__ __forceinline__ uint32_t packf2(float a, float b) {
    __half2 t = __floats2half2_rn(a, b);
    return *reinterpret_cast<uint32_t*>(&t);
}
__device__ __forceinline__ void cp16(uint32_t s, const void* g) {
    asm volatile("cp.async.cg.shared.global [%0], [%1], 16;" :: "r"(s), "l"(g));
}
__device__ __forceinline__ void cp_commit() {
    asm volatile("cp.async.commit_group;");
}
template <int N> __device__ __forceinline__ void cp_wait() {
    asm volatile("cp.async.wait_group %0;" :: "n"(N));
}
__device__ __forceinline__ void ldm_x4(uint32_t* r, uint32_t a) {
    asm volatile("ldmatrix.sync.aligned.m8n8.x4.shared.b16 {%0,%1,%2,%3}, [%4];"
                 : "=r"(r[0]), "=r"(r[1]), "=r"(r[2]), "=r"(r[3]) : "r"(a));
}
__device__ __forceinline__ void ldm_x4t(uint32_t* r, uint32_t a) {
    asm volatile("ldmatrix.sync.aligned.m8n8.x4.trans.shared.b16 {%0,%1,%2,%3}, [%4];"
                 : "=r"(r[0]), "=r"(r[1]), "=r"(r[2]), "=r"(r[3]) : "r"(a));
}
__device__ __forceinline__ void mma16816(float* d, const uint32_t* a, uint32_t b0, uint32_t b1) {
    asm volatile(
        "mma.sync.aligned.m16n8k16.row.col.f32.f16.f16.f32 "
        "{%0,%1,%2,%3}, {%4,%5,%6,%7}, {%8,%9}, {%0,%1,%2,%3};"
        : "+f"(d[0]), "+f"(d[1]), "+f"(d[2]), "+f"(d[3])
        : "r"(a[0]), "r"(a[1]), "r"(a[2]), "r"(a[3]), "r"(b0), "r"(b1));
}

// ============================================================================
// conversions
// ============================================================================
// All 4 weights: fp32 [K,N] -> transposed fp16 [N][K], one launch
__global__ __launch_bounds__(256) void conv_w4(
    const float* __restrict__ W0, const float* __restrict__ W1,
    const float* __restrict__ W2, const float* __restrict__ W3,
    __half* __restrict__ dst)
{
    const int w = blockIdx.y;
    const float* W = (w == 0) ? W0 : (w == 1) ? W1 : (w == 2) ? W2 : W3;
    __half* d = dst + (size_t)w * DMODEL * DMODEL;
    int idx = blockIdx.x * 256 + threadIdx.x;
    int kg = idx >> 10, n = idx & 1023;
    int k0 = kg * 4;
    float a0 = W[(size_t)(k0 + 0) * DMODEL + n];
    float a1 = W[(size_t)(k0 + 1) * DMODEL + n];
    float a2 = W[(size_t)(k0 + 2) * DMODEL + n];
    float a3 = W[(size_t)(k0 + 3) * DMODEL + n];
    *(uint2*)(d + (size_t)n * DMODEL + k0) = make_uint2(packf2(a0, a1), packf2(a2, a3));
}

// Q/K/V fp32 -> fp16 planes, fully coalesced, one launch
__global__ __launch_bounds__(256) void conv_a3(
    const float* __restrict__ Q, const float* __restrict__ K,
    const float* __restrict__ V, __half* __restrict__ dst, int M)
{
    const int z = blockIdx.y;
    const float* src = (z == 0) ? Q : (z == 1) ? K : V;
    __half* d = dst + (size_t)z * MMAX * DMODEL;
    size_t idx = ((size_t)blockIdx.x * 256 + threadIdx.x) * 8;
    if (idx >= (size_t)M * DMODEL) return;
    float4 v0 = *(const float4*)(src + idx);
    float4 v1 = *(const float4*)(src + idx + 4);
    uint4 o;
    o.x = packf2(v0.x, v0.y); o.y = packf2(v0.z, v0.w);
    o.z = packf2(v1.x, v1.y); o.w = packf2(v1.z, v1.w);
    *(uint4*)(d + idx) = o;
}

// ============================================================================
// fp16 GEMM core: BK=64 stages, 128 threads, 4 warps (2x2), warp tile 64x64.
// One __syncthreads per 128 MMAs/warp. 144B-strided smem rows (proven in attn).
// mode 0: fp32 C; 1: hi/lo fp16 BHSD; 2: single fp16 BHSD
// ============================================================================
#define SRW   144                 // 64 fp16 = 128B + 16 pad
#define PLN   (128 * SRW)         // 18432
#define STG   (2 * PLN)           // A + W = 36864
#define GEMM_SMEM (2 * STG)       // 73728

__device__ __forceinline__ void gemm16_core(
    const __half* __restrict__ A, const __half* __restrict__ W,
    const float* __restrict__ bias, float* __restrict__ C,
    __half* __restrict__ outH, __half* __restrict__ outL,
    unsigned char* dyn, int M, int mode, float scale)
{
    const uint32_t sbase = smem_u32(dyn);
    const int tid = threadIdx.x, lane = tid & 31, wid = tid >> 5;
    const int mw = wid >> 1, nw = wid & 1;
    const int rowBase = blockIdx.y * 128, colBase = blockIdx.x * 128;

    const __half* aB = A + (size_t)rowBase * DMODEL;
    const __half* bB = W + (size_t)colBase * DMODEL;

    auto load_stage = [&](int kt, int s) {
        const uint32_t sb = sbase + s * STG;
        #pragma unroll
        for (int i = 0; i < 8; i++) {
            int c = tid + 128 * i;            // 1024 chunks per plane
            int r = c >> 3, col = (c & 7) * 16;
            cp16(sb + r * SRW + col,       (const char*)(aB + (size_t)r * DMODEL + kt * 64) + col);
            cp16(sb + PLN + r * SRW + col, (const char*)(bB + (size_t)r * DMODEL + kt * 64) + col);
        }
    };

    float acc[4][8][4] = {};
    const int lr = lane & 15, lc = lane >> 4;

    load_stage(0, 0);
    cp_commit();

    const int NIT = DMODEL / 64;              // 16
    for (int kt = 0; kt < NIT; kt++) {
        const int s = kt & 1;
        cp_wait<0>();
        __syncthreads();                      // stage s ready; stage s^1 free
        if (kt + 1 < NIT) {
            load_stage(kt + 1, s ^ 1);
            cp_commit();
        }

        const uint32_t sb = sbase + s * STG;
        #pragma unroll
        for (int kk = 0; kk < 4; kk++) {
            uint32_t ah[4][4], bh[4][4];
            #pragma unroll
            for (int mi = 0; mi < 4; mi++)
                ldm_x4(ah[mi], sb + (mw * 64 + mi * 16 + lr) * SRW + kk * 32 + lc * 16);
            #pragma unroll
            for (int ni = 0; ni < 4; ni++)
                ldm_x4(bh[ni], sb + PLN + (nw * 64 + ni * 16 + lr) * SRW + kk * 32 + lc * 16);
            #pragma unroll
            for (int mi = 0; mi < 4; mi++) {
                #pragma unroll
                for (int n8 = 0; n8 < 8; n8++) {
                    const int ni = n8 >> 1, hf = n8 & 1;
                    mma16816(acc[mi][n8], ah[mi], bh[ni][hf], bh[ni][hf + 2]);
                }
            }
        }
    }

    const int wr = rowBase + mw * 64, wc = colBase + nw * 64;
    #pragma unroll
    for (int mi = 0; mi < 4; mi++) {
        #pragma unroll
        for (int n8 = 0; n8 < 8; n8++) {
            const int col = wc + n8 * 8 + (lane & 3) * 2;
            const float b0 = bias[col], b1 = bias[col + 1];
            #pragma unroll
            for (int h = 0; h < 2; h++) {
                const int row = wr + mi * 16 + (lane >> 2) + 8 * h;
                float ox = (acc[mi][n8][2 * h + 0] + b0) * scale;
                float oy = (acc[mi][n8][2 * h + 1] + b1) * scale;
                if (mode == 0) {
                    float2 o; o.x = ox; o.y = oy;
                    *(float2*)&C[(size_t)row * DMODEL + col] = o;
                } else {
                    int bb = row >> 11, ss = row & 2047;
                    int hh = col >> 6, dd = col & 63;
                    size_t e = ((size_t)(bb * NHEADS + hh) * S_LEN + ss) * DK + dd;
                    if (mode == 1) {
                        __half hx, lx, hy, ly;
                        split2h(ox, hx, lx); split2h(oy, hy, ly);
                        *(uint32_t*)(outH + e) = pack2h(hx, hy);
                        *(uint32_t*)(outL + e) = pack2h(lx, ly);
                    } else {
                        *(uint32_t*)(outH + e) = packf2(ox, oy);
                    }
                }
            }
        }
    }
}

// fused Q/K/V projection: blockIdx.z selects input/weight/bias/output
__global__ __launch_bounds__(128) void gemm_qkv(
    const __half* __restrict__ xP, const __half* __restrict__ wP,
    const float* __restrict__ bq, const float* __restrict__ bk, const float* __restrict__ bv,
    __half* __restrict__ qh, __half* __restrict__ ql,
    __half* __restrict__ kh, __half* __restrict__ vh, int M)
{
    extern __shared__ unsigned char dyn[];
    const int z = blockIdx.z;
    const __half* A = xP + (size_t)z * MMAX * DMODEL;
    const __half* W = wP + (size_t)z * DMODEL * DMODEL;
    const float* bias = (z == 0) ? bq : (z == 1) ? bk : bv;
    __half* oH = (z == 0) ? qh : (z == 1) ? kh : vh;
    __half* oL = (z == 0) ? ql : nullptr;
    gemm16_core(A, W, bias, nullptr, oH, oL, dyn, M,
                (z == 0) ? 1 : 2, (z == 0) ? 0.125f : 1.0f);
}

// output projection
__global__ __launch_bounds__(128) void gemm_o(
    const __half* __restrict__ A, const __half* __restrict__ W,
    const float* __restrict__ bias, float* __restrict__ C, int M)
{
    extern __shared__ unsigned char dyn[];
    gemm16_core(A, W, bias, C, nullptr, nullptr, dyn, M, 0, 1.0f);
}

// ============================================================================
// FA2 attention (verified round-8/9, unchanged): fp16, Q hi/lo 2-pass QK^T,
// single-pass P·V. CTA: 128 q-rows, 4 warps x 32 q-rows.
// ============================================================================
#define AT_SROW  144
#define AT_PLANE (64 * AT_SROW)
#define AT_STAGE (2 * AT_PLANE)
#define ATT_SMEM (2 * AT_STAGE)

__global__ __launch_bounds__(128) void attn_mma(
    const __half* __restrict__ qhG, const __half* __restrict__ qlG,
    const __half* __restrict__ khG, const __half* __restrict__ vhG,
    __half* __restrict__ outA)
{
    extern __shared__ unsigned char dyn[];
    const uint32_t sb = smem_u32(dyn);
    const int tid = threadIdx.x, lane = tid & 31, wid = tid >> 5;
    const int q0 = blockIdx.x * 128, h = blockIdx.y, b = blockIdx.z;
    const size_t hb = (size_t)(b * NHEADS + h) * S_LEN * DK;

    const char* qhB = (const char*)(qhG + hb);
    const char* qlB = (const char*)(qlG + hb);
    const char* khB = (const char*)(khG + hb);
    const char* vhB = (const char*)(vhG + hb);

    #pragma unroll
    for (int i = 0; i < 16; i++) {
        int cid = tid + 128 * i;
        int pl = cid >> 10;
        int r  = (cid >> 3) & 127;
        int c  = (cid & 7) * 16;
        const char* g = (pl ? qlB : qhB) + (size_t)(q0 + r) * (DK * 2) + c;
        cp16(sb + pl * (128 * AT_SROW) + r * AT_SROW + c, g);
    }
    cp_commit(); cp_wait<0>(); __syncthreads();

    const int lr = lane & 15, lc = lane >> 4;
    uint32_t qfh[2][4][4], qfl[2][4][4];
    #pragma unroll
    for (int mi = 0; mi < 2; mi++) {
        #pragma unroll
        for (int ks = 0; ks < 4; ks++) {
            uint32_t a = sb + (wid * 32 + mi * 16 + lr) * AT_SROW + ks * 32 + lc * 16;
            ldm_x4(qfh[mi][ks], a);
            ldm_x4(qfl[mi][ks], a + 128 * AT_SROW);
        }
    }
    __syncthreads();

    float o[2][8][4] = {};
    float mS[2][2] = {{-1e30f, -1e30f}, {-1e30f, -1e30f}};
    float lS[2][2] = {};

    auto load_kv = [&](int t, int s) {
        const uint32_t st = sb + s * AT_STAGE;
        #pragma unroll
        for (int i = 0; i < 8; i++) {
            int cid = tid + 128 * i;
            int pl = cid >> 9;
            int r  = (cid >> 3) & 63;
            int c  = (cid & 7) * 16;
            const char* g = (pl == 0) ? khB : vhB;
            g += (size_t)(t * 64 + r) * (DK * 2) + c;
            cp16(st + pl * AT_PLANE + r * AT_SROW + c, g);
        }
    };

    load_kv(0, 0);
    cp_commit();

    const int NT = S_LEN / 64;
    for (int t = 0; t < NT; t++) {
        if (t + 1 < NT) load_kv(t + 1, (t + 1) & 1);
        cp_commit();
        cp_wait<1>();
        __syncthreads();
        const uint32_t st = sb + (t & 1) * AT_STAGE;

        float s[2][8][4] = {};
        #pragma unroll
        for (int g = 0; g < 4; g++) {
            #pragma unroll
            for (int ks = 0; ks < 4; ks++) {
                uint32_t kf[4];
                uint32_t a = st + (g * 16 + lr) * AT_SROW + ks * 32 + lc * 16;
                ldm_x4(kf, a);
                #pragma unroll
                for (int mi = 0; mi < 2; mi++) {
                    #pragma unroll
                    for (int hf = 0; hf < 2; hf++) {
                        mma16816(s[mi][2 * g + hf], qfh[mi][ks], kf[hf], kf[hf + 2]);
                        mma16816(s[mi][2 * g + hf], qfl[mi][ks], kf[hf], kf[hf + 2]);
                    }
                }
            }
        }

        uint32_t ph[2][4][4];
        #pragma unroll
        for (int mi = 0; mi < 2; mi++) {
            float mx0 = -1e30f, mx1 = -1e30f;
            #pragma unroll
            for (int j = 0; j < 8; j++) {
                mx0 = fmaxf(mx0, fmaxf(s[mi][j][0], s[mi][j][1]));
                mx1 = fmaxf(mx1, fmaxf(s[mi][j][2], s[mi][j][3]));
            }
            mx0 = fmaxf(mx0, __shfl_xor_sync(0xffffffffu, mx0, 1));
            mx0 = fmaxf(mx0, __shfl_xor_sync(0xffffffffu, mx0, 2));
            mx1 = fmaxf(mx1, __shfl_xor_sync(0xffffffffu, mx1, 1));
            mx1 = fmaxf(mx1, __shfl_xor_sync(0xffffffffu, mx1, 2));
            const float mn0 = fmaxf(mS[mi][0], mx0), mn1 = fmaxf(mS[mi][1], mx1);
            const float c0 = __expf(mS[mi][0] - mn0), c1 = __expf(mS[mi][1] - mn1);
            float ls0 = 0.f, ls1 = 0.f;
            #pragma unroll
            for (int j = 0; j < 8; j++) {
                s[mi][j][0] = __expf(s[mi][j][0] - mn0);
                s[mi][j][1] = __expf(s[mi][j][1] - mn0);
                s[mi][j][2] = __expf(s[mi][j][2] - mn1);
                s[mi][j][3] = __expf(s[mi][j][3] - mn1);
                ls0 += s[mi][j][0] + s[mi][j][1];
                ls1 += s[mi][j][2] + s[mi][j][3];
            }
            ls0 += __shfl_xor_sync(0xffffffffu, ls0, 1);
            ls0 += __shfl_xor_sync(0xffffffffu, ls0, 2);
            ls1 += __shfl_xor_sync(0xffffffffu, ls1, 1);
            ls1 += __shfl_xor_sync(0xffffffffu, ls1, 2);
            lS[mi][0] = lS[mi][0] * c0 + ls0;
            lS[mi][1] = lS[mi][1] * c1 + ls1;
            mS[mi][0] = mn0;  mS[mi][1] = mn1;
            #pragma unroll
            for (int j = 0; j < 8; j++) {
                o[mi][j][0] *= c0; o[mi][j][1] *= c0;
                o[mi][j][2] *= c1; o[mi][j][3] *= c1;
            }
            #pragma unroll
            for (int k = 0; k < 4; k++) {
                #pragma unroll
                for (int u = 0; u < 4; u++) {
                    const int jt = 2 * k + (u >> 1);
                    const int e  = (u & 1) * 2;
                    ph[mi][k][u] = packf2(s[mi][jt][e + 0], s[mi][jt][e + 1]);
                }
            }
        }

        #pragma unroll
        for (int d = 0; d < 4; d++) {
            #pragma unroll
            for (int k = 0; k < 4; k++) {
                uint32_t vf[4];
                uint32_t a = st + AT_PLANE + (k * 16 + lr) * AT_SROW + d * 32 + lc * 16;
                ldm_x4t(vf, a);
                #pragma unroll
                for (int mi = 0; mi < 2; mi++) {
                    mma16816(o[mi][2 * d + 0], ph[mi][k], vf[0], vf[1]);
                    mma16816(o[mi][2 * d + 1], ph[mi][k], vf[2], vf[3]);
                }
            }
        }
        __syncthreads();
    }

    const int cb = (lane & 3) * 2;
    #pragma unroll
    for (int mi = 0; mi < 2; mi++) {
        const float inv0 = 1.0f / lS[mi][0], inv1 = 1.0f / lS[mi][1];
        const int row0 = q0 + wid * 32 + mi * 16 + (lane >> 2);
        #pragma unroll
        for (int j = 0; j < 8; j++) {
            const int col = h * DK + j * 8 + cb;
            const size_t e0 = ((size_t)b * S_LEN + row0) * DMODEL + col;
            const size_t e1 = e0 + 8 * DMODEL;
            *(uint32_t*)(outA + e0) = packf2(o[mi][j][0] * inv0, o[mi][j][1] * inv0);
            *(uint32_t*)(outA + e1) = packf2(o[mi][j][2] * inv1, o[mi][j][3] * inv1);
        }
    }
}

// ============================================================================
extern "C" void kernel_launch(void* const* d_in, const int* in_sizes, int n_in,
                              void* d_out, int out_size)
{
    const float* Q  = (const float*)d_in[0];
    const float* K_ = (const float*)d_in[1];
    const float* V  = (const float*)d_in[2];
    const float* Wq = (const float*)d_in[3];
    const float* bq = (const float*)d_in[4];
    const float* Wk = (const float*)d_in[5];
    const float* bk = (const float*)d_in[6];
    const float* Wv = (const float*)d_in[7];
    const float* bv = (const float*)d_in[8];
    const float* Wo = (const float*)d_in[9];
    const float* bo = (const float*)d_in[10];

    int B = in_sizes[0] / (S_LEN * DMODEL);
    if (B > MAXB) B = MAXB;
    const int M = B * S_LEN;

    __half *xP, *aP, *wP, *qh, *ql, *kh, *vh;
    cudaGetSymbolAddress((void**)&xP, g_x16);
    cudaGetSymbolAddress((void**)&aP, g_a16);
    cudaGetSymbolAddress((void**)&wP, g_w16);
    cudaGetSymbolAddress((void**)&qh, g_qh);
    cudaGetSymbolAddress((void**)&ql, g_ql);
    cudaGetSymbolAddress((void**)&kh, g_kh);
    cudaGetSymbolAddress((void**)&vh, g_vh);
    const size_t WSZ = (size_t)DMODEL * DMODEL;

    cudaFuncSetAttribute(gemm_qkv, cudaFuncAttributeMaxDynamicSharedMemorySize, GEMM_SMEM);
    cudaFuncSetAttribute(gemm_o,   cudaFuncAttributeMaxDynamicSharedMemorySize, GEMM_SMEM);
    cudaFuncSetAttribute(attn_mma, cudaFuncAttributeMaxDynamicSharedMemorySize, ATT_SMEM);

    conv_w4<<<dim3(1024, 4), 256>>>(Wq, Wk, Wv, Wo, wP);
    conv_a3<<<dim3(M * DMODEL / 2048, 3), 256>>>(Q, K_, V, xP, M);

    gemm_qkv<<<dim3(DMODEL / 128, M / 128, 3), 128, GEMM_SMEM>>>(
        xP, wP, bq, bk, bv, qh, ql, kh, vh, M);

    attn_mma<<<dim3(S_LEN / 128, NHEADS, B), 128, ATT_SMEM>>>(qh, ql, kh, vh, aP);

    gemm_o<<<dim3(DMODEL / 128, M / 128), 128, GEMM_SMEM>>>(
        aP, wP + 3 * WSZ, bo, (float*)d_out, M);
}